// round 1
// baseline (speedup 1.0000x reference)
#include <cuda_runtime.h>
#include <math.h>

// Problem constants
#define BATCH   2
#define SEQ     2048
#define CDIM    1024
#define HEADS   16
#define HDIM    64
#define GAMMA_F 8.0f
#define SCALE_F 0.125f
#define MROWS   (BATCH*SEQ)          // 4096

// ---------------- scratch (device globals; no allocation allowed) ----------
__device__ float g_qraw[MROWS * 2 * CDIM];   // 8.4M floats
__device__ float g_kraw[MROWS * 2 * CDIM];
__device__ float g_v   [MROWS * CDIM];
__device__ float g_qr  [MROWS * CDIM];
__device__ float g_qi  [MROWS * CDIM];
__device__ float g_kr  [MROWS * CDIM];
__device__ float g_ki  [MROWS * CDIM];
__device__ float g_att [MROWS * CDIM];

// ---------------- SGEMM: C = A(MxK) * B(KxN), row-major, 128x128x8 --------
__global__ __launch_bounds__(256)
void sgemm128(const float* __restrict__ A, const float* __restrict__ Bm,
              float* __restrict__ Cm, int M, int N, int K) {
    __shared__ float As[8][128];
    __shared__ float Bs[8][128];
    const int tid = threadIdx.x;
    const int tx = tid & 15, ty = tid >> 4;
    const int m0 = blockIdx.y * 128, n0 = blockIdx.x * 128;

    float acc[8][8];
#pragma unroll
    for (int i = 0; i < 8; i++)
#pragma unroll
        for (int j = 0; j < 8; j++) acc[i][j] = 0.f;

    const int arow = tid >> 1;            // 0..127
    const int akq  = (tid & 1) * 4;       // 0 or 4
    const int brow = tid >> 5;            // 0..7
    const int bcol = (tid & 31) * 4;      // 0..124

    const float* Aptr = A + (size_t)(m0 + arow) * K + akq;
    const float* Bptr = Bm + (size_t)brow * N + n0 + bcol;

    for (int k0 = 0; k0 < K; k0 += 8) {
        float4 av = *(const float4*)(Aptr + k0);
        As[akq + 0][arow] = av.x;
        As[akq + 1][arow] = av.y;
        As[akq + 2][arow] = av.z;
        As[akq + 3][arow] = av.w;
        float4 bv = *(const float4*)(Bptr + (size_t)k0 * N);
        *(float4*)&Bs[brow][bcol] = bv;
        __syncthreads();
#pragma unroll
        for (int k = 0; k < 8; k++) {
            float4 a0 = *(float4*)&As[k][ty * 8];
            float4 a1 = *(float4*)&As[k][ty * 8 + 4];
            float4 b0 = *(float4*)&Bs[k][tx * 8];
            float4 b1 = *(float4*)&Bs[k][tx * 8 + 4];
            float a[8] = {a0.x, a0.y, a0.z, a0.w, a1.x, a1.y, a1.z, a1.w};
            float b[8] = {b0.x, b0.y, b0.z, b0.w, b1.x, b1.y, b1.z, b1.w};
#pragma unroll
            for (int i = 0; i < 8; i++)
#pragma unroll
                for (int j = 0; j < 8; j++) acc[i][j] = fmaf(a[i], b[j], acc[i][j]);
        }
        __syncthreads();
    }

#pragma unroll
    for (int i = 0; i < 8; i++) {
        float4 c0 = make_float4(acc[i][0], acc[i][1], acc[i][2], acc[i][3]);
        float4 c1 = make_float4(acc[i][4], acc[i][5], acc[i][6], acc[i][7]);
        float* dst = Cm + (size_t)(m0 + ty * 8 + i) * N + n0 + tx * 8;
        *(float4*)dst = c0;
        *(float4*)(dst + 4) = c1;
    }
}

// ---------------- amp/phase transform -------------------------------------
__device__ __forceinline__ float softplus_f(float a) {
    return (a > 20.f) ? a : log1pf(expf(a));
}

__global__ __launch_bounds__(256)
void transform_qk() {
    int idx = blockIdx.x * 256 + threadIdx.x;      // < MROWS*CDIM
    int bt = idx >> 10;
    int c  = idx & 1023;
    size_t rbase = (size_t)bt * (2 * CDIM);

    float qa = g_qraw[rbase + c];
    float qp = g_qraw[rbase + CDIM + c];
    float ka = g_kraw[rbase + c];
    float kp = g_kraw[rbase + CDIM + c];

    float qs = softplus_f(qa), ks = softplus_f(ka);
    float sq, cq, sk, ck;
    sincosf(qp, &sq, &cq);
    sincosf(kp, &sk, &ck);

    g_qr[idx] = qs * cq;
    g_qi[idx] = qs * sq;
    g_kr[idx] = ks * ck;
    g_ki[idx] = ks * sk;
}

// ---------------- flash attention with moiré gate --------------------------
// Tile: 64 queries x 64 keys, D=64. 256 threads = 16x16 grid, 4x4 microtiles.
#define ASTR 68
#define ASMEM_FLOATS (6 * 64 * ASTR)

__global__ __launch_bounds__(256)
void attn_kernel(const float* __restrict__ theta) {
    extern __shared__ float sm[];
    float* sQr = sm;
    float* sQi = sQr + 64 * ASTR;
    float* sKr = sQi + 64 * ASTR;
    float* sKi = sKr + 64 * ASTR;
    float* sV  = sKi + 64 * ASTR;   // [s][d]
    float* sP  = sV  + 64 * ASTR;   // [s][qrow]

    const int tid = threadIdx.x;
    const int tx = tid & 15, ty = tid >> 4;
    const int q0 = blockIdx.x * 64;
    const int h  = blockIdx.y;
    const int b  = blockIdx.z;
    const float th = theta[h] * (1.0f / GAMMA_F);

    // load Q tile (transposed: [d][row])
    const size_t baseQ = ((size_t)(b * SEQ + q0)) * CDIM + h * HDIM;
#pragma unroll
    for (int i = 0; i < 16; i++) {
        int idx = tid + i * 256;
        int r = idx >> 6, d = idx & 63;
        sQr[d * ASTR + r] = g_qr[baseQ + (size_t)r * CDIM + d];
        sQi[d * ASTR + r] = g_qi[baseQ + (size_t)r * CDIM + d];
    }

    // per-row query angles (gate separability: cos(th*(s-t)) = cs*cq + ss*sq)
    float cq[4], sq[4];
#pragma unroll
    for (int i = 0; i < 4; i++) {
        float a = th * (float)(q0 + ty * 4 + i);
        sincosf(a, &sq[i], &cq[i]);
    }

    float mrow[4], lrow[4], o[4][4];
#pragma unroll
    for (int i = 0; i < 4; i++) {
        mrow[i] = -INFINITY;
        lrow[i] = 0.f;
#pragma unroll
        for (int j = 0; j < 4; j++) o[i][j] = 0.f;
    }
    __syncthreads();

    for (int s0 = 0; s0 <= q0; s0 += 64) {
        // load K, V tiles
        const size_t baseK = ((size_t)(b * SEQ + s0)) * CDIM + h * HDIM;
#pragma unroll
        for (int i = 0; i < 16; i++) {
            int idx = tid + i * 256;
            int r = idx >> 6, d = idx & 63;
            sKr[d * ASTR + r] = g_kr[baseK + (size_t)r * CDIM + d];
            sKi[d * ASTR + r] = g_ki[baseK + (size_t)r * CDIM + d];
            sV [r * ASTR + d] = g_v [baseK + (size_t)r * CDIM + d];
        }
        __syncthreads();

        // S = Qr.Kr^T + Qi.Ki^T
        float acc[4][4];
#pragma unroll
        for (int i = 0; i < 4; i++)
#pragma unroll
            for (int j = 0; j < 4; j++) acc[i][j] = 0.f;

#pragma unroll 8
        for (int d = 0; d < 64; d++) {
            float4 q4r = *(float4*)&sQr[d * ASTR + ty * 4];
            float4 q4i = *(float4*)&sQi[d * ASTR + ty * 4];
            float4 k4r = *(float4*)&sKr[d * ASTR + tx * 4];
            float4 k4i = *(float4*)&sKi[d * ASTR + tx * 4];
            float qr[4] = {q4r.x, q4r.y, q4r.z, q4r.w};
            float qi[4] = {q4i.x, q4i.y, q4i.z, q4i.w};
            float kr[4] = {k4r.x, k4r.y, k4r.z, k4r.w};
            float ki[4] = {k4i.x, k4i.y, k4i.z, k4i.w};
#pragma unroll
            for (int i = 0; i < 4; i++)
#pragma unroll
                for (int j = 0; j < 4; j++)
                    acc[i][j] = fmaf(qi[i], ki[j], fmaf(qr[i], kr[j], acc[i][j]));
        }

        // key-side gate angles
        float cs[4], sn[4];
#pragma unroll
        for (int j = 0; j < 4; j++) {
            float a = th * (float)(s0 + tx * 4 + j);
            sincosf(a, &sn[j], &cs[j]);
        }

        // gate + scale + causal mask, streaming softmax, store P
#pragma unroll
        for (int i = 0; i < 4; i++) {
            const int trow = q0 + ty * 4 + i;
            float sc[4];
            float tmax = -INFINITY;
#pragma unroll
            for (int j = 0; j < 4; j++) {
                float gate = cs[j] * cq[i] + sn[j] * sq[i];
                float v = acc[i][j] * SCALE_F * gate;
                int scol = s0 + tx * 4 + j;
                sc[j] = (scol <= trow) ? v : -INFINITY;
                tmax = fmaxf(tmax, sc[j]);
            }
            // reduce max over the 16 lanes owning this row
            tmax = fmaxf(tmax, __shfl_xor_sync(0xffffffffu, tmax, 1));
            tmax = fmaxf(tmax, __shfl_xor_sync(0xffffffffu, tmax, 2));
            tmax = fmaxf(tmax, __shfl_xor_sync(0xffffffffu, tmax, 4));
            tmax = fmaxf(tmax, __shfl_xor_sync(0xffffffffu, tmax, 8));

            float mn = fmaxf(mrow[i], tmax);
            float corr = __expf(mrow[i] - mn);
            float rs = 0.f;
            float p[4];
#pragma unroll
            for (int j = 0; j < 4; j++) {
                p[j] = __expf(sc[j] - mn);
                rs += p[j];
            }
            rs += __shfl_xor_sync(0xffffffffu, rs, 1);
            rs += __shfl_xor_sync(0xffffffffu, rs, 2);
            rs += __shfl_xor_sync(0xffffffffu, rs, 4);
            rs += __shfl_xor_sync(0xffffffffu, rs, 8);

            lrow[i] = lrow[i] * corr + rs;
            mrow[i] = mn;
#pragma unroll
            for (int j = 0; j < 4; j++) o[i][j] *= corr;
#pragma unroll
            for (int j = 0; j < 4; j++)
                sP[(size_t)(tx * 4 + j) * ASTR + ty * 4 + i] = p[j];
        }
        __syncthreads();

        // O += P @ V
#pragma unroll 8
        for (int s = 0; s < 64; s++) {
            float4 p4 = *(float4*)&sP[s * ASTR + ty * 4];
            float4 v4 = *(float4*)&sV[s * ASTR + tx * 4];
            float p[4] = {p4.x, p4.y, p4.z, p4.w};
            float v[4] = {v4.x, v4.y, v4.z, v4.w};
#pragma unroll
            for (int i = 0; i < 4; i++)
#pragma unroll
                for (int j = 0; j < 4; j++) o[i][j] = fmaf(p[i], v[j], o[i][j]);
        }
        __syncthreads();
    }

    // normalize and write to (B,T,C) layout for the output projection
#pragma unroll
    for (int i = 0; i < 4; i++) {
        float inv = 1.0f / lrow[i];
        float4 ov = make_float4(o[i][0] * inv, o[i][1] * inv,
                                o[i][2] * inv, o[i][3] * inv);
        size_t dst = ((size_t)(b * SEQ + q0 + ty * 4 + i)) * CDIM + h * HDIM + tx * 4;
        *(float4*)&g_att[dst] = ov;
    }
}

// ---------------- launch ---------------------------------------------------
extern "C" void kernel_launch(void* const* d_in, const int* in_sizes, int n_in,
                              void* d_out, int out_size) {
    const float* x     = (const float*)d_in[0];
    const float* Wq    = (const float*)d_in[1];
    const float* Wk    = (const float*)d_in[2];
    const float* Wv    = (const float*)d_in[3];
    const float* Wo    = (const float*)d_in[4];
    const float* theta = (const float*)d_in[5];
    float* out = (float*)d_out;

    float *qraw, *kraw, *v, *att;
    cudaGetSymbolAddress((void**)&qraw, g_qraw);
    cudaGetSymbolAddress((void**)&kraw, g_kraw);
    cudaGetSymbolAddress((void**)&v,    g_v);
    cudaGetSymbolAddress((void**)&att,  g_att);

    dim3 blk(256);
    dim3 gQK(2 * CDIM / 128, MROWS / 128);   // (16, 32)
    dim3 gV(CDIM / 128, MROWS / 128);        // (8, 32)

    sgemm128<<<gQK, blk>>>(x, Wq, qraw, MROWS, 2 * CDIM, CDIM);
    sgemm128<<<gQK, blk>>>(x, Wk, kraw, MROWS, 2 * CDIM, CDIM);
    sgemm128<<<gV,  blk>>>(x, Wv, v,    MROWS, CDIM, CDIM);

    transform_qk<<<MROWS * CDIM / 256, blk>>>();

    const int smem_bytes = ASMEM_FLOATS * (int)sizeof(float);  // 104448
    cudaFuncSetAttribute(attn_kernel,
                         cudaFuncAttributeMaxDynamicSharedMemorySize, smem_bytes);
    attn_kernel<<<dim3(SEQ / 64, HEADS, BATCH), blk, smem_bytes>>>(theta);

    sgemm128<<<gV, blk>>>(att, Wo, out, MROWS, CDIM, CDIM);
}

// round 3
// speedup vs baseline: 1.6957x; 1.6957x over previous
#include <cuda_runtime.h>
#include <cuda_bf16.h>
#include <cstdint>
#include <math.h>

// Problem constants
#define BATCH   2
#define SEQ     2048
#define CDIM    1024
#define HEADS   16
#define HDIM    64
#define GAMMA_F 8.0f
#define SCALE_F 0.125f
#define MROWS   (BATCH*SEQ)          // 4096
#define KDIM    1024                 // contraction dim for every GEMM here

// ---------------- scratch (device globals; no allocation allowed) ----------
__device__ float g_qraw[MROWS * 2 * CDIM];
__device__ float g_kraw[MROWS * 2 * CDIM];
__device__ float g_v   [MROWS * CDIM];
__device__ float g_qr  [MROWS * CDIM];
__device__ float g_qi  [MROWS * CDIM];
__device__ float g_kr  [MROWS * CDIM];
__device__ float g_ki  [MROWS * CDIM];
__device__ float g_att [MROWS * CDIM];

// split-bf16 operands
__device__ __nv_bfloat16 g_xh [MROWS * CDIM];
__device__ __nv_bfloat16 g_xl [MROWS * CDIM];
__device__ __nv_bfloat16 g_ah [MROWS * CDIM];
__device__ __nv_bfloat16 g_al [MROWS * CDIM];
__device__ __nv_bfloat16 g_wqh[2 * CDIM * CDIM];
__device__ __nv_bfloat16 g_wql[2 * CDIM * CDIM];
__device__ __nv_bfloat16 g_wkh[2 * CDIM * CDIM];
__device__ __nv_bfloat16 g_wkl[2 * CDIM * CDIM];
__device__ __nv_bfloat16 g_wvh[CDIM * CDIM];
__device__ __nv_bfloat16 g_wvl[CDIM * CDIM];
__device__ __nv_bfloat16 g_woh[CDIM * CDIM];
__device__ __nv_bfloat16 g_wol[CDIM * CDIM];

// ---------------- helpers ---------------------------------------------------
__device__ __forceinline__ uint32_t smem_u32(const void* p) {
    uint32_t a;
    asm("{ .reg .u64 t; cvta.to.shared.u64 t, %1; cvt.u32.u64 %0, t; }"
        : "=r"(a) : "l"(p));
    return a;
}
#define SWZ128(o) ((o) ^ (((o) >> 3) & 0x70))

__device__ __forceinline__ void cp_async16(uint32_t dst, const void* src) {
    asm volatile("cp.async.cg.shared.global [%0], [%1], 16;" :: "r"(dst), "l"(src));
}

__device__ __forceinline__ void ldsm_x4(uint32_t& r0, uint32_t& r1,
                                        uint32_t& r2, uint32_t& r3, uint32_t addr) {
    asm volatile("ldmatrix.sync.aligned.m8n8.x4.shared.b16 {%0,%1,%2,%3}, [%4];"
                 : "=r"(r0), "=r"(r1), "=r"(r2), "=r"(r3) : "r"(addr));
}

__device__ __forceinline__ void mma_bf16(float* c, const uint32_t* a,
                                         uint32_t b0, uint32_t b1) {
    asm volatile(
        "mma.sync.aligned.m16n8k16.row.col.f32.bf16.bf16.f32 "
        "{%0,%1,%2,%3}, {%4,%5,%6,%7}, {%8,%9}, {%0,%1,%2,%3};"
        : "+f"(c[0]), "+f"(c[1]), "+f"(c[2]), "+f"(c[3])
        : "r"(a[0]), "r"(a[1]), "r"(a[2]), "r"(a[3]), "r"(b0), "r"(b1));
}

// ---------------- split-bf16 GEMM: C[M,N] = A[M,K] * B[N,K]^T ---------------
// Tile 128x128, K-chunk 64, 8 warps of 64x32, mma.sync m16n8k16, hi/lo 3-MMA.
#define BK       64
#define NCH      (KDIM / BK)             // 16
#define TILE_B   16384                   // 128 rows * 128B
#define BUF_B    (4 * TILE_B)            // Ah Al Bh Bl
#define GEMM_SMEM (2 * BUF_B)            // 131072

__device__ __forceinline__ void load_tile(uint32_t sdst, const __nv_bfloat16* gsrc,
                                          int tid) {
#pragma unroll
    for (int it = 0; it < 4; it++) {
        int idx = tid + it * 256;
        int r = idx >> 3;                 // 0..127
        int u = idx & 7;                  // 16B units
        uint32_t off = (uint32_t)(r * 128 + u * 16);
        cp_async16(sdst + SWZ128(off), gsrc + (size_t)r * KDIM + u * 8);
    }
}

__global__ __launch_bounds__(256)
void gemm_bf16x3(const __nv_bfloat16* __restrict__ Ah, const __nv_bfloat16* __restrict__ Al,
                 const __nv_bfloat16* __restrict__ Bh, const __nv_bfloat16* __restrict__ Bl,
                 float* __restrict__ Cm, int N) {
    extern __shared__ char smem[];
    const uint32_t sb = smem_u32(smem);
    const int tid = threadIdx.x, wid = tid >> 5, lane = tid & 31;
    const int m0 = blockIdx.y * 128, n0 = blockIdx.x * 128;
    const int wm = (wid & 1) * 64;
    const int wn = (wid >> 1) * 32;

    const __nv_bfloat16* gAh = Ah + (size_t)m0 * KDIM;
    const __nv_bfloat16* gAl = Al + (size_t)m0 * KDIM;
    const __nv_bfloat16* gBh = Bh + (size_t)n0 * KDIM;
    const __nv_bfloat16* gBl = Bl + (size_t)n0 * KDIM;

    float acc[4][4][4];
#pragma unroll
    for (int i = 0; i < 4; i++)
#pragma unroll
        for (int j = 0; j < 4; j++)
#pragma unroll
            for (int e = 0; e < 4; e++) acc[i][j][e] = 0.f;

    // precomputed ldmatrix lane offsets (relative, unswizzled)
    const int a_row = (lane & 15);
    const uint32_t a_cb = (uint32_t)((lane >> 4) * 16);
    const int b_row = ((lane >> 4) & 1) * 8 + (lane & 7);
    const uint32_t b_cb = (uint32_t)(((lane >> 3) & 1) * 16);

    // preload chunk 0 into buffer 0
    load_tile(sb,              gAh, tid);
    load_tile(sb + TILE_B,     gAl, tid);
    load_tile(sb + 2 * TILE_B, gBh, tid);
    load_tile(sb + 3 * TILE_B, gBl, tid);
    asm volatile("cp.async.commit_group;");

    for (int i = 0; i < NCH; i++) {
        if (i + 1 < NCH) {
            const int kc = (i + 1) * BK;
            const uint32_t nb = sb + ((i + 1) & 1) * BUF_B;
            load_tile(nb,              gAh + kc, tid);
            load_tile(nb + TILE_B,     gAl + kc, tid);
            load_tile(nb + 2 * TILE_B, gBh + kc, tid);
            load_tile(nb + 3 * TILE_B, gBl + kc, tid);
            asm volatile("cp.async.commit_group;");
            asm volatile("cp.async.wait_group 1;" ::: "memory");
        } else {
            asm volatile("cp.async.wait_group 0;" ::: "memory");
        }
        __syncthreads();

        const uint32_t bb = sb + (i & 1) * BUF_B;
        const uint32_t aH = bb, aL = bb + TILE_B;
        const uint32_t bH = bb + 2 * TILE_B, bL = bb + 3 * TILE_B;

#pragma unroll
        for (int ks = 0; ks < 4; ks++) {
            const uint32_t kb = (uint32_t)(ks * 32);
            uint32_t ah[4][4], al[4][4];
#pragma unroll
            for (int mi = 0; mi < 4; mi++) {
                uint32_t off = SWZ128((uint32_t)((wm + mi * 16 + a_row) * 128) + kb + a_cb);
                ldsm_x4(ah[mi][0], ah[mi][1], ah[mi][2], ah[mi][3], aH + off);
                ldsm_x4(al[mi][0], al[mi][1], al[mi][2], al[mi][3], aL + off);
            }
            uint32_t bh[2][4], bl[2][4];
#pragma unroll
            for (int g = 0; g < 2; g++) {
                uint32_t off = SWZ128((uint32_t)((wn + g * 16 + b_row) * 128) + kb + b_cb);
                ldsm_x4(bh[g][0], bh[g][1], bh[g][2], bh[g][3], bH + off);
                ldsm_x4(bl[g][0], bl[g][1], bl[g][2], bl[g][3], bL + off);
            }
#pragma unroll
            for (int mi = 0; mi < 4; mi++) {
#pragma unroll
                for (int nj = 0; nj < 4; nj++) {
                    const int g = nj >> 1, p = (nj & 1) * 2;
                    mma_bf16(acc[mi][nj], ah[mi], bh[g][p], bh[g][p + 1]);
                    mma_bf16(acc[mi][nj], ah[mi], bl[g][p], bl[g][p + 1]);
                    mma_bf16(acc[mi][nj], al[mi], bh[g][p], bh[g][p + 1]);
                }
            }
        }
        __syncthreads();
    }

    // epilogue: write fp32
    const int cr = lane >> 2;
    const int cc = (lane & 3) * 2;
#pragma unroll
    for (int mi = 0; mi < 4; mi++) {
#pragma unroll
        for (int nj = 0; nj < 4; nj++) {
            const int r = m0 + wm + mi * 16 + cr;
            const int c = n0 + wn + nj * 8 + cc;
            *(float2*)&Cm[(size_t)r * N + c] = make_float2(acc[mi][nj][0], acc[mi][nj][1]);
            *(float2*)&Cm[(size_t)(r + 8) * N + c] = make_float2(acc[mi][nj][2], acc[mi][nj][3]);
        }
    }
}

// ---------------- fp32 -> (hi,lo) bf16 split -------------------------------
__global__ __launch_bounds__(256)
void convert_split(const float* __restrict__ src, __nv_bfloat16* __restrict__ hi,
                   __nv_bfloat16* __restrict__ lo) {
    int i = blockIdx.x * 256 + threadIdx.x;
    float4 v = ((const float4*)src)[i];
    float f[4] = {v.x, v.y, v.z, v.w};
    __nv_bfloat16 h[4], l[4];
#pragma unroll
    for (int j = 0; j < 4; j++) {
        h[j] = __float2bfloat16(f[j]);
        l[j] = __float2bfloat16(f[j] - __bfloat162float(h[j]));
    }
    *(__nv_bfloat162*)(hi + 4 * (size_t)i)     = __nv_bfloat162(h[0], h[1]);
    *(__nv_bfloat162*)(hi + 4 * (size_t)i + 2) = __nv_bfloat162(h[2], h[3]);
    *(__nv_bfloat162*)(lo + 4 * (size_t)i)     = __nv_bfloat162(l[0], l[1]);
    *(__nv_bfloat162*)(lo + 4 * (size_t)i + 2) = __nv_bfloat162(l[2], l[3]);
}

// ---------------- weight transpose + split: W[K,N] -> out[N,K] bf16 hi/lo ---
__global__ __launch_bounds__(256)
void transpose_split(const float* __restrict__ W, __nv_bfloat16* __restrict__ Hh,
                     __nv_bfloat16* __restrict__ Hl, int K, int N) {
    __shared__ float t[32][33];
    const int tx = threadIdx.x, ty = threadIdx.y;   // 32 x 8
    const int n0 = blockIdx.x * 32, k0 = blockIdx.y * 32;
#pragma unroll
    for (int i = 0; i < 32; i += 8)
        t[ty + i][tx] = W[(size_t)(k0 + ty + i) * N + n0 + tx];
    __syncthreads();
#pragma unroll
    for (int i = 0; i < 32; i += 8) {
        float v = t[tx][ty + i];
        __nv_bfloat16 h = __float2bfloat16(v);
        Hh[(size_t)(n0 + ty + i) * K + k0 + tx] = h;
        Hl[(size_t)(n0 + ty + i) * K + k0 + tx] =
            __float2bfloat16(v - __bfloat162float(h));
    }
}

// ---------------- amp/phase transform -------------------------------------
__device__ __forceinline__ float softplus_f(float a) {
    return (a > 20.f) ? a : log1pf(expf(a));
}

__global__ __launch_bounds__(256)
void transform_qk() {
    int idx = blockIdx.x * 256 + threadIdx.x;
    int bt = idx >> 10;
    int c  = idx & 1023;
    size_t rbase = (size_t)bt * (2 * CDIM);

    float qa = g_qraw[rbase + c];
    float qp = g_qraw[rbase + CDIM + c];
    float ka = g_kraw[rbase + c];
    float kp = g_kraw[rbase + CDIM + c];

    float qs = softplus_f(qa), ks = softplus_f(ka);
    float sq, cq, sk, ck;
    sincosf(qp, &sq, &cq);
    sincosf(kp, &sk, &ck);

    g_qr[idx] = qs * cq;
    g_qi[idx] = qs * sq;
    g_kr[idx] = ks * ck;
    g_ki[idx] = ks * sk;
}

// ---------------- flash attention with moiré gate --------------------------
#define ASTR 68
#define ASMEM_FLOATS (6 * 64 * ASTR)

__global__ __launch_bounds__(256)
void attn_kernel(const float* __restrict__ theta) {
    extern __shared__ float sm[];
    float* sQr = sm;
    float* sQi = sQr + 64 * ASTR;
    float* sKr = sQi + 64 * ASTR;
    float* sKi = sKr + 64 * ASTR;
    float* sV  = sKi + 64 * ASTR;
    float* sP  = sV  + 64 * ASTR;

    const int tid = threadIdx.x;
    const int tx = tid & 15, ty = tid >> 4;
    const int q0 = blockIdx.x * 64;
    const int h  = blockIdx.y;
    const int b  = blockIdx.z;
    const float th = theta[h] * (1.0f / GAMMA_F);

    const size_t baseQ = ((size_t)(b * SEQ + q0)) * CDIM + h * HDIM;
#pragma unroll
    for (int i = 0; i < 16; i++) {
        int idx = tid + i * 256;
        int r = idx >> 6, d = idx & 63;
        sQr[d * ASTR + r] = g_qr[baseQ + (size_t)r * CDIM + d];
        sQi[d * ASTR + r] = g_qi[baseQ + (size_t)r * CDIM + d];
    }

    float cq[4], sq[4];
#pragma unroll
    for (int i = 0; i < 4; i++) {
        float a = th * (float)(q0 + ty * 4 + i);
        sincosf(a, &sq[i], &cq[i]);
    }

    float mrow[4], lrow[4], o[4][4];
#pragma unroll
    for (int i = 0; i < 4; i++) {
        mrow[i] = -INFINITY;
        lrow[i] = 0.f;
#pragma unroll
        for (int j = 0; j < 4; j++) o[i][j] = 0.f;
    }
    __syncthreads();

    for (int s0 = 0; s0 <= q0; s0 += 64) {
        const size_t baseK = ((size_t)(b * SEQ + s0)) * CDIM + h * HDIM;
#pragma unroll
        for (int i = 0; i < 16; i++) {
            int idx = tid + i * 256;
            int r = idx >> 6, d = idx & 63;
            sKr[d * ASTR + r] = g_kr[baseK + (size_t)r * CDIM + d];
            sKi[d * ASTR + r] = g_ki[baseK + (size_t)r * CDIM + d];
            sV [r * ASTR + d] = g_v [baseK + (size_t)r * CDIM + d];
        }
        __syncthreads();

        float acc[4][4];
#pragma unroll
        for (int i = 0; i < 4; i++)
#pragma unroll
            for (int j = 0; j < 4; j++) acc[i][j] = 0.f;

#pragma unroll 8
        for (int d = 0; d < 64; d++) {
            float4 q4r = *(float4*)&sQr[d * ASTR + ty * 4];
            float4 q4i = *(float4*)&sQi[d * ASTR + ty * 4];
            float4 k4r = *(float4*)&sKr[d * ASTR + tx * 4];
            float4 k4i = *(float4*)&sKi[d * ASTR + tx * 4];
            float qr[4] = {q4r.x, q4r.y, q4r.z, q4r.w};
            float qi[4] = {q4i.x, q4i.y, q4i.z, q4i.w};
            float kr[4] = {k4r.x, k4r.y, k4r.z, k4r.w};
            float ki[4] = {k4i.x, k4i.y, k4i.z, k4i.w};
#pragma unroll
            for (int i = 0; i < 4; i++)
#pragma unroll
                for (int j = 0; j < 4; j++)
                    acc[i][j] = fmaf(qi[i], ki[j], fmaf(qr[i], kr[j], acc[i][j]));
        }

        float cs[4], sn[4];
#pragma unroll
        for (int j = 0; j < 4; j++) {
            float a = th * (float)(s0 + tx * 4 + j);
            sincosf(a, &sn[j], &cs[j]);
        }

#pragma unroll
        for (int i = 0; i < 4; i++) {
            const int trow = q0 + ty * 4 + i;
            float sc[4];
            float tmax = -INFINITY;
#pragma unroll
            for (int j = 0; j < 4; j++) {
                float gate = cs[j] * cq[i] + sn[j] * sq[i];
                float v = acc[i][j] * SCALE_F * gate;
                int scol = s0 + tx * 4 + j;
                sc[j] = (scol <= trow) ? v : -INFINITY;
                tmax = fmaxf(tmax, sc[j]);
            }
            tmax = fmaxf(tmax, __shfl_xor_sync(0xffffffffu, tmax, 1));
            tmax = fmaxf(tmax, __shfl_xor_sync(0xffffffffu, tmax, 2));
            tmax = fmaxf(tmax, __shfl_xor_sync(0xffffffffu, tmax, 4));
            tmax = fmaxf(tmax, __shfl_xor_sync(0xffffffffu, tmax, 8));

            float mn = fmaxf(mrow[i], tmax);
            float corr = __expf(mrow[i] - mn);
            float rs = 0.f;
            float p[4];
#pragma unroll
            for (int j = 0; j < 4; j++) {
                p[j] = __expf(sc[j] - mn);
                rs += p[j];
            }
            rs += __shfl_xor_sync(0xffffffffu, rs, 1);
            rs += __shfl_xor_sync(0xffffffffu, rs, 2);
            rs += __shfl_xor_sync(0xffffffffu, rs, 4);
            rs += __shfl_xor_sync(0xffffffffu, rs, 8);

            lrow[i] = lrow[i] * corr + rs;
            mrow[i] = mn;
#pragma unroll
            for (int j = 0; j < 4; j++) o[i][j] *= corr;
#pragma unroll
            for (int j = 0; j < 4; j++)
                sP[(size_t)(tx * 4 + j) * ASTR + ty * 4 + i] = p[j];
        }
        __syncthreads();

#pragma unroll 8
        for (int s = 0; s < 64; s++) {
            float4 p4 = *(float4*)&sP[s * ASTR + ty * 4];
            float4 v4 = *(float4*)&sV[s * ASTR + tx * 4];
            float p[4] = {p4.x, p4.y, p4.z, p4.w};
            float v[4] = {v4.x, v4.y, v4.z, v4.w};
#pragma unroll
            for (int i = 0; i < 4; i++)
#pragma unroll
                for (int j = 0; j < 4; j++) o[i][j] = fmaf(p[i], v[j], o[i][j]);
        }
        __syncthreads();
    }

#pragma unroll
    for (int i = 0; i < 4; i++) {
        float inv = 1.0f / lrow[i];
        float4 ov = make_float4(o[i][0] * inv, o[i][1] * inv,
                                o[i][2] * inv, o[i][3] * inv);
        size_t dst = ((size_t)(b * SEQ + q0 + ty * 4 + i)) * CDIM + h * HDIM + tx * 4;
        *(float4*)&g_att[dst] = ov;
    }
}

// ---------------- launch ---------------------------------------------------
extern "C" void kernel_launch(void* const* d_in, const int* in_sizes, int n_in,
                              void* d_out, int out_size) {
    const float* x     = (const float*)d_in[0];
    const float* Wq    = (const float*)d_in[1];
    const float* Wk    = (const float*)d_in[2];
    const float* Wv    = (const float*)d_in[3];
    const float* Wo    = (const float*)d_in[4];
    const float* theta = (const float*)d_in[5];
    float* out = (float*)d_out;

    float *qraw, *kraw, *v, *att;
    __nv_bfloat16 *xh, *xl, *ah, *al, *wqh, *wql, *wkh, *wkl, *wvh, *wvl, *woh, *wol;
    cudaGetSymbolAddress((void**)&qraw, g_qraw);
    cudaGetSymbolAddress((void**)&kraw, g_kraw);
    cudaGetSymbolAddress((void**)&v,    g_v);
    cudaGetSymbolAddress((void**)&att,  g_att);
    cudaGetSymbolAddress((void**)&xh,  g_xh);
    cudaGetSymbolAddress((void**)&xl,  g_xl);
    cudaGetSymbolAddress((void**)&ah,  g_ah);
    cudaGetSymbolAddress((void**)&al,  g_al);
    cudaGetSymbolAddress((void**)&wqh, g_wqh);
    cudaGetSymbolAddress((void**)&wql, g_wql);
    cudaGetSymbolAddress((void**)&wkh, g_wkh);
    cudaGetSymbolAddress((void**)&wkl, g_wkl);
    cudaGetSymbolAddress((void**)&wvh, g_wvh);
    cudaGetSymbolAddress((void**)&wvl, g_wvl);
    cudaGetSymbolAddress((void**)&woh, g_woh);
    cudaGetSymbolAddress((void**)&wol, g_wol);

    cudaFuncSetAttribute(gemm_bf16x3,
                         cudaFuncAttributeMaxDynamicSharedMemorySize, GEMM_SMEM);
    cudaFuncSetAttribute(attn_kernel,
                         cudaFuncAttributeMaxDynamicSharedMemorySize,
                         ASMEM_FLOATS * (int)sizeof(float));

    dim3 tblk(32, 8);
    transpose_split<<<dim3(2 * CDIM / 32, CDIM / 32), tblk>>>(Wq, wqh, wql, CDIM, 2 * CDIM);
    transpose_split<<<dim3(2 * CDIM / 32, CDIM / 32), tblk>>>(Wk, wkh, wkl, CDIM, 2 * CDIM);
    transpose_split<<<dim3(CDIM / 32, CDIM / 32), tblk>>>(Wv, wvh, wvl, CDIM, CDIM);
    transpose_split<<<dim3(CDIM / 32, CDIM / 32), tblk>>>(Wo, woh, wol, CDIM, CDIM);

    convert_split<<<MROWS * CDIM / 4 / 256, 256>>>(x, xh, xl);

    gemm_bf16x3<<<dim3(2 * CDIM / 128, MROWS / 128), 256, GEMM_SMEM>>>(xh, xl, wqh, wql, qraw, 2 * CDIM);
    gemm_bf16x3<<<dim3(2 * CDIM / 128, MROWS / 128), 256, GEMM_SMEM>>>(xh, xl, wkh, wkl, kraw, 2 * CDIM);
    gemm_bf16x3<<<dim3(CDIM / 128, MROWS / 128), 256, GEMM_SMEM>>>(xh, xl, wvh, wvl, v, CDIM);

    transform_qk<<<MROWS * CDIM / 256, 256>>>();

    attn_kernel<<<dim3(SEQ / 64, HEADS, BATCH), 256, ASMEM_FLOATS * (int)sizeof(float)>>>(theta);

    convert_split<<<MROWS * CDIM / 4 / 256, 256>>>(att, ah, al);
    gemm_bf16x3<<<dim3(CDIM / 128, MROWS / 128), 256, GEMM_SMEM>>>(ah, al, woh, wol, out, CDIM);
}

// round 4
// speedup vs baseline: 2.0865x; 1.2305x over previous
#include <cuda_runtime.h>
#include <cuda_bf16.h>
#include <cstdint>
#include <math.h>

// Problem constants
#define BATCH   2
#define SEQ     2048
#define CDIM    1024
#define HEADS   16
#define HDIM    64
#define GAMMA_F 8.0f
#define SCALE_F 0.125f
#define MROWS   (BATCH*SEQ)          // 4096
#define KDIM    1024

// ---------------- scratch (device globals; no allocation allowed) ----------
__device__ float g_qraw[MROWS * 2 * CDIM];
__device__ float g_kraw[MROWS * 2 * CDIM];
__device__ float g_v   [MROWS * CDIM];

// split-bf16 operands
__device__ __nv_bfloat16 g_xh [MROWS * CDIM];
__device__ __nv_bfloat16 g_xl [MROWS * CDIM];
__device__ __nv_bfloat16 g_ah [MROWS * CDIM];
__device__ __nv_bfloat16 g_al [MROWS * CDIM];
__device__ __nv_bfloat16 g_wqh[2 * CDIM * CDIM];
__device__ __nv_bfloat16 g_wql[2 * CDIM * CDIM];
__device__ __nv_bfloat16 g_wkh[2 * CDIM * CDIM];
__device__ __nv_bfloat16 g_wkl[2 * CDIM * CDIM];
__device__ __nv_bfloat16 g_wvh[CDIM * CDIM];
__device__ __nv_bfloat16 g_wvl[CDIM * CDIM];
__device__ __nv_bfloat16 g_woh[CDIM * CDIM];
__device__ __nv_bfloat16 g_wol[CDIM * CDIM];

// attention operands, split bf16
__device__ __nv_bfloat16 g_qrh[MROWS * CDIM];
__device__ __nv_bfloat16 g_qrl[MROWS * CDIM];
__device__ __nv_bfloat16 g_qih[MROWS * CDIM];
__device__ __nv_bfloat16 g_qil[MROWS * CDIM];
__device__ __nv_bfloat16 g_krh[MROWS * CDIM];
__device__ __nv_bfloat16 g_krl[MROWS * CDIM];
__device__ __nv_bfloat16 g_kih[MROWS * CDIM];
__device__ __nv_bfloat16 g_kil[MROWS * CDIM];
__device__ __nv_bfloat16 g_vh [MROWS * CDIM];
__device__ __nv_bfloat16 g_vl [MROWS * CDIM];
__device__ float2 g_gate[HEADS * SEQ];

// ---------------- helpers ---------------------------------------------------
__device__ __forceinline__ uint32_t smem_u32(const void* p) {
    uint32_t a;
    asm("{ .reg .u64 t; cvta.to.shared.u64 t, %1; cvt.u32.u64 %0, t; }"
        : "=r"(a) : "l"(p));
    return a;
}
#define SWZ128(o) ((o) ^ (((o) >> 3) & 0x70))

__device__ __forceinline__ void cp_async16(uint32_t dst, const void* src) {
    asm volatile("cp.async.cg.shared.global [%0], [%1], 16;" :: "r"(dst), "l"(src));
}

__device__ __forceinline__ void ldsm_x4(uint32_t& r0, uint32_t& r1,
                                        uint32_t& r2, uint32_t& r3, uint32_t addr) {
    asm volatile("ldmatrix.sync.aligned.m8n8.x4.shared.b16 {%0,%1,%2,%3}, [%4];"
                 : "=r"(r0), "=r"(r1), "=r"(r2), "=r"(r3) : "r"(addr));
}
__device__ __forceinline__ void ldsm_x4_t(uint32_t& r0, uint32_t& r1,
                                          uint32_t& r2, uint32_t& r3, uint32_t addr) {
    asm volatile("ldmatrix.sync.aligned.m8n8.x4.trans.shared.b16 {%0,%1,%2,%3}, [%4];"
                 : "=r"(r0), "=r"(r1), "=r"(r2), "=r"(r3) : "r"(addr));
}

__device__ __forceinline__ void mma_bf16(float* c, const uint32_t* a,
                                         uint32_t b0, uint32_t b1) {
    asm volatile(
        "mma.sync.aligned.m16n8k16.row.col.f32.bf16.bf16.f32 "
        "{%0,%1,%2,%3}, {%4,%5,%6,%7}, {%8,%9}, {%0,%1,%2,%3};"
        : "+f"(c[0]), "+f"(c[1]), "+f"(c[2]), "+f"(c[3])
        : "r"(a[0]), "r"(a[1]), "r"(a[2]), "r"(a[3]), "r"(b0), "r"(b1));
}

__device__ __forceinline__ uint32_t pack_bf16(float a, float b) {
    __nv_bfloat162 t = __float22bfloat162_rn(make_float2(a, b));  // a -> low
    return *reinterpret_cast<uint32_t*>(&t);
}

// ---------------- split-bf16 GEMM (unchanged from R3, validated) ------------
#define BK       64
#define NCH      (KDIM / BK)
#define TILE_B   16384
#define BUF_B    (4 * TILE_B)
#define GEMM_SMEM (2 * BUF_B)

__device__ __forceinline__ void load_tile(uint32_t sdst, const __nv_bfloat16* gsrc,
                                          int tid) {
#pragma unroll
    for (int it = 0; it < 4; it++) {
        int idx = tid + it * 256;
        int r = idx >> 3;
        int u = idx & 7;
        uint32_t off = (uint32_t)(r * 128 + u * 16);
        cp_async16(sdst + SWZ128(off), gsrc + (size_t)r * KDIM + u * 8);
    }
}

__global__ __launch_bounds__(256)
void gemm_bf16x3(const __nv_bfloat16* __restrict__ Ah, const __nv_bfloat16* __restrict__ Al,
                 const __nv_bfloat16* __restrict__ Bh, const __nv_bfloat16* __restrict__ Bl,
                 float* __restrict__ Cm, int N) {
    extern __shared__ char smem[];
    const uint32_t sb = smem_u32(smem);
    const int tid = threadIdx.x, wid = tid >> 5, lane = tid & 31;
    const int m0 = blockIdx.y * 128, n0 = blockIdx.x * 128;
    const int wm = (wid & 1) * 64;
    const int wn = (wid >> 1) * 32;

    const __nv_bfloat16* gAh = Ah + (size_t)m0 * KDIM;
    const __nv_bfloat16* gAl = Al + (size_t)m0 * KDIM;
    const __nv_bfloat16* gBh = Bh + (size_t)n0 * KDIM;
    const __nv_bfloat16* gBl = Bl + (size_t)n0 * KDIM;

    float acc[4][4][4];
#pragma unroll
    for (int i = 0; i < 4; i++)
#pragma unroll
        for (int j = 0; j < 4; j++)
#pragma unroll
            for (int e = 0; e < 4; e++) acc[i][j][e] = 0.f;

    const int a_row = (lane & 15);
    const uint32_t a_cb = (uint32_t)((lane >> 4) * 16);
    const int b_row = ((lane >> 4) & 1) * 8 + (lane & 7);
    const uint32_t b_cb = (uint32_t)(((lane >> 3) & 1) * 16);

    load_tile(sb,              gAh, tid);
    load_tile(sb + TILE_B,     gAl, tid);
    load_tile(sb + 2 * TILE_B, gBh, tid);
    load_tile(sb + 3 * TILE_B, gBl, tid);
    asm volatile("cp.async.commit_group;");

    for (int i = 0; i < NCH; i++) {
        if (i + 1 < NCH) {
            const int kc = (i + 1) * BK;
            const uint32_t nb = sb + ((i + 1) & 1) * BUF_B;
            load_tile(nb,              gAh + kc, tid);
            load_tile(nb + TILE_B,     gAl + kc, tid);
            load_tile(nb + 2 * TILE_B, gBh + kc, tid);
            load_tile(nb + 3 * TILE_B, gBl + kc, tid);
            asm volatile("cp.async.commit_group;");
            asm volatile("cp.async.wait_group 1;" ::: "memory");
        } else {
            asm volatile("cp.async.wait_group 0;" ::: "memory");
        }
        __syncthreads();

        const uint32_t bb = sb + (i & 1) * BUF_B;
        const uint32_t aH = bb, aL = bb + TILE_B;
        const uint32_t bH = bb + 2 * TILE_B, bL = bb + 3 * TILE_B;

#pragma unroll
        for (int ks = 0; ks < 4; ks++) {
            const uint32_t kb = (uint32_t)(ks * 32);
            uint32_t ah[4][4], al[4][4];
#pragma unroll
            for (int mi = 0; mi < 4; mi++) {
                uint32_t off = SWZ128((uint32_t)((wm + mi * 16 + a_row) * 128) + kb + a_cb);
                ldsm_x4(ah[mi][0], ah[mi][1], ah[mi][2], ah[mi][3], aH + off);
                ldsm_x4(al[mi][0], al[mi][1], al[mi][2], al[mi][3], aL + off);
            }
            uint32_t bh[2][4], bl[2][4];
#pragma unroll
            for (int g = 0; g < 2; g++) {
                uint32_t off = SWZ128((uint32_t)((wn + g * 16 + b_row) * 128) + kb + b_cb);
                ldsm_x4(bh[g][0], bh[g][1], bh[g][2], bh[g][3], bH + off);
                ldsm_x4(bl[g][0], bl[g][1], bl[g][2], bl[g][3], bL + off);
            }
#pragma unroll
            for (int mi = 0; mi < 4; mi++) {
#pragma unroll
                for (int nj = 0; nj < 4; nj++) {
                    const int g = nj >> 1, p = (nj & 1) * 2;
                    mma_bf16(acc[mi][nj], ah[mi], bh[g][p], bh[g][p + 1]);
                    mma_bf16(acc[mi][nj], ah[mi], bl[g][p], bl[g][p + 1]);
                    mma_bf16(acc[mi][nj], al[mi], bh[g][p], bh[g][p + 1]);
                }
            }
        }
        __syncthreads();
    }

    const int cr = lane >> 2;
    const int cc = (lane & 3) * 2;
#pragma unroll
    for (int mi = 0; mi < 4; mi++) {
#pragma unroll
        for (int nj = 0; nj < 4; nj++) {
            const int r = m0 + wm + mi * 16 + cr;
            const int c = n0 + wn + nj * 8 + cc;
            *(float2*)&Cm[(size_t)r * N + c] = make_float2(acc[mi][nj][0], acc[mi][nj][1]);
            *(float2*)&Cm[(size_t)(r + 8) * N + c] = make_float2(acc[mi][nj][2], acc[mi][nj][3]);
        }
    }
}

// ---------------- fp32 -> (hi,lo) bf16 split -------------------------------
__global__ __launch_bounds__(256)
void convert_split(const float* __restrict__ src, __nv_bfloat16* __restrict__ hi,
                   __nv_bfloat16* __restrict__ lo) {
    int i = blockIdx.x * 256 + threadIdx.x;
    float4 v = ((const float4*)src)[i];
    float f[4] = {v.x, v.y, v.z, v.w};
    __nv_bfloat16 h[4], l[4];
#pragma unroll
    for (int j = 0; j < 4; j++) {
        h[j] = __float2bfloat16(f[j]);
        l[j] = __float2bfloat16(f[j] - __bfloat162float(h[j]));
    }
    *(__nv_bfloat162*)(hi + 4 * (size_t)i)     = __nv_bfloat162(h[0], h[1]);
    *(__nv_bfloat162*)(hi + 4 * (size_t)i + 2) = __nv_bfloat162(h[2], h[3]);
    *(__nv_bfloat162*)(lo + 4 * (size_t)i)     = __nv_bfloat162(l[0], l[1]);
    *(__nv_bfloat162*)(lo + 4 * (size_t)i + 2) = __nv_bfloat162(l[2], l[3]);
}

// ---------------- weight transpose + split ---------------------------------
__global__ __launch_bounds__(256)
void transpose_split(const float* __restrict__ W, __nv_bfloat16* __restrict__ Hh,
                     __nv_bfloat16* __restrict__ Hl, int K, int N) {
    __shared__ float t[32][33];
    const int tx = threadIdx.x, ty = threadIdx.y;
    const int n0 = blockIdx.x * 32, k0 = blockIdx.y * 32;
#pragma unroll
    for (int i = 0; i < 32; i += 8)
        t[ty + i][tx] = W[(size_t)(k0 + ty + i) * N + n0 + tx];
    __syncthreads();
#pragma unroll
    for (int i = 0; i < 32; i += 8) {
        float v = t[tx][ty + i];
        __nv_bfloat16 h = __float2bfloat16(v);
        Hh[(size_t)(n0 + ty + i) * K + k0 + tx] = h;
        Hl[(size_t)(n0 + ty + i) * K + k0 + tx] =
            __float2bfloat16(v - __bfloat162float(h));
    }
}

// ---------------- amp/phase transform -> split bf16 -------------------------
__device__ __forceinline__ float softplus_f(float a) {
    return (a > 20.f) ? a : log1pf(expf(a));
}
__device__ __forceinline__ void split2(float a, float b, __nv_bfloat16* H,
                                       __nv_bfloat16* L, size_t idx) {
    __nv_bfloat16 ha = __float2bfloat16(a), hb = __float2bfloat16(b);
    *(__nv_bfloat162*)(H + idx) = __nv_bfloat162(ha, hb);
    *(__nv_bfloat162*)(L + idx) = __nv_bfloat162(
        __float2bfloat16(a - __bfloat162float(ha)),
        __float2bfloat16(b - __bfloat162float(hb)));
}

__global__ __launch_bounds__(256)
void transform_qk_bf16() {
    int i2 = blockIdx.x * 256 + threadIdx.x;       // handles 2 consecutive c
    int c2 = i2 * 2;
    int bt = c2 >> 10;
    int c  = c2 & 1023;
    size_t rbase = (size_t)bt * (2 * CDIM);
    size_t oidx  = (size_t)bt * CDIM + c;

    float qa0 = g_qraw[rbase + c],        qa1 = g_qraw[rbase + c + 1];
    float qp0 = g_qraw[rbase + CDIM + c], qp1 = g_qraw[rbase + CDIM + c + 1];
    float ka0 = g_kraw[rbase + c],        ka1 = g_kraw[rbase + c + 1];
    float kp0 = g_kraw[rbase + CDIM + c], kp1 = g_kraw[rbase + CDIM + c + 1];

    float qs0 = softplus_f(qa0), qs1 = softplus_f(qa1);
    float ks0 = softplus_f(ka0), ks1 = softplus_f(ka1);
    float s0, c0, s1, c1, s2, c2f, s3, c3;
    sincosf(qp0, &s0, &c0); sincosf(qp1, &s1, &c1);
    sincosf(kp0, &s2, &c2f); sincosf(kp1, &s3, &c3);

    split2(qs0 * c0, qs1 * c1, g_qrh, g_qrl, oidx);
    split2(qs0 * s0, qs1 * s1, g_qih, g_qil, oidx);
    split2(ks0 * c2f, ks1 * c3, g_krh, g_krl, oidx);
    split2(ks0 * s2, ks1 * s3, g_kih, g_kil, oidx);
}

__global__ void gate_init(const float* __restrict__ theta) {
    int i = blockIdx.x * 256 + threadIdx.x;        // < HEADS*SEQ
    int h = i >> 11, s = i & (SEQ - 1);
    float th = theta[h] * (1.0f / GAMMA_F);
    float sn, cs;
    sincosf(th * (float)s, &sn, &cs);
    g_gate[i] = make_float2(cs, sn);
}

// ---------------- tensor-core flash attention with moiré gate ---------------
// Q-tile 128, S-tile 64, 8 warps x 16 q-rows. Split-bf16 3-MMA everywhere.
#define AQT 128
#define AST 64
#define AQ_TILE 16384                       // 128 rows * 128B
#define AKV_TILE 8192                       // 64 rows * 128B
#define AKV_BUF (6 * AKV_TILE)              // krh,krl,kih,kil,vh,vl
#define ATT_SMEM (4 * AQ_TILE + 2 * AKV_BUF)  // 163840

__global__ __launch_bounds__(256)
void attn_mma() {
    extern __shared__ char smem[];
    const uint32_t sQ  = smem_u32(smem);
    const uint32_t sKV = sQ + 4 * AQ_TILE;

    const int tid = threadIdx.x, w = tid >> 5, lane = tid & 31;
    const int q0 = (int)(gridDim.x - 1 - blockIdx.x) * AQT;
    const int h = blockIdx.y, b = blockIdx.z;

    const __nv_bfloat16* qs[4]  = {g_qrh, g_qrl, g_qih, g_qil};
    const __nv_bfloat16* kvs[6] = {g_krh, g_krl, g_kih, g_kil, g_vh, g_vl};

    // ldmatrix lane patterns (validated in gemm_bf16x3)
    const int a_row = lane & 15;
    const uint32_t a_cb = (uint32_t)((lane >> 4) * 16);
    const int b_row = ((lane >> 4) & 1) * 8 + (lane & 7);
    const uint32_t b_cb = (uint32_t)(((lane >> 3) & 1) * 16);

    // Q tiles (once)
#pragma unroll
    for (int it = 0; it < 16; it++) {
        int idx = tid + it * 256;
        int tile = idx >> 10, rr = (idx >> 3) & 127, u = idx & 7;
        cp_async16(sQ + tile * AQ_TILE + SWZ128((uint32_t)(rr * 128 + u * 16)),
                   qs[tile] + ((size_t)(b * SEQ + q0 + rr) * CDIM + h * HDIM + u * 8));
    }
    asm volatile("cp.async.commit_group;");

    const int nS = q0 / AST + 2;

    // preload KV tile 0
#pragma unroll
    for (int it = 0; it < 12; it++) {
        int idx = tid + it * 256;
        int tile = idx >> 9, rr = (idx >> 3) & 63, u = idx & 7;
        cp_async16(sKV + tile * AKV_TILE + SWZ128((uint32_t)(rr * 128 + u * 16)),
                   kvs[tile] + ((size_t)(b * SEQ + rr) * CDIM + h * HDIM + u * 8));
    }
    asm volatile("cp.async.commit_group;");

    // per-thread row state
    const int t0g = q0 + w * 16 + (lane >> 2);
    const int t1g = t0g + 8;
    const float2 gt0 = g_gate[h * SEQ + t0g];
    const float2 gt1 = g_gate[h * SEQ + t1g];

    float m0 = -INFINITY, m1 = -INFINITY, l0 = 0.f, l1 = 0.f;
    float oacc[8][4];
#pragma unroll
    for (int f = 0; f < 8; f++)
#pragma unroll
        for (int e = 0; e < 4; e++) oacc[f][e] = 0.f;

    for (int i = 0; i < nS; i++) {
        if (i + 1 < nS) {
            const int s0n = (i + 1) * AST;
            const uint32_t nb = sKV + ((i + 1) & 1) * AKV_BUF;
#pragma unroll
            for (int it = 0; it < 12; it++) {
                int idx = tid + it * 256;
                int tile = idx >> 9, rr = (idx >> 3) & 63, u = idx & 7;
                cp_async16(nb + tile * AKV_TILE + SWZ128((uint32_t)(rr * 128 + u * 16)),
                           kvs[tile] + ((size_t)(b * SEQ + s0n + rr) * CDIM + h * HDIM + u * 8));
            }
            asm volatile("cp.async.commit_group;");
            asm volatile("cp.async.wait_group 1;" ::: "memory");
        } else {
            asm volatile("cp.async.wait_group 0;" ::: "memory");
        }
        __syncthreads();

        const int s0 = i * AST;
        const uint32_t kb0 = sKV + (i & 1) * AKV_BUF;
        const uint32_t kRH = kb0, kRL = kb0 + AKV_TILE;
        const uint32_t kIH = kb0 + 2 * AKV_TILE, kIL = kb0 + 3 * AKV_TILE;
        const uint32_t vH = kb0 + 4 * AKV_TILE, vL = kb0 + 5 * AKV_TILE;

        // ---- S = Qr.Kr^T + Qi.Ki^T (split-bf16 3-MMA each) ----
        float sacc[8][4];
#pragma unroll
        for (int f = 0; f < 8; f++)
#pragma unroll
            for (int e = 0; e < 4; e++) sacc[f][e] = 0.f;

#pragma unroll
        for (int jd = 0; jd < 4; jd++) {
            const uint32_t kb = (uint32_t)(jd * 32);
            const uint32_t offA = SWZ128((uint32_t)((w * 16 + a_row) * 128) + kb + a_cb);
            uint32_t arh[4], arl[4], aih[4], ail[4];
            ldsm_x4(arh[0], arh[1], arh[2], arh[3], sQ + offA);
            ldsm_x4(arl[0], arl[1], arl[2], arl[3], sQ + AQ_TILE + offA);
            ldsm_x4(aih[0], aih[1], aih[2], aih[3], sQ + 2 * AQ_TILE + offA);
            ldsm_x4(ail[0], ail[1], ail[2], ail[3], sQ + 3 * AQ_TILE + offA);
#pragma unroll
            for (int g = 0; g < 4; g++) {
                const uint32_t offB = SWZ128((uint32_t)((g * 16 + b_row) * 128) + kb + b_cb);
                uint32_t rh[4], rl[4], ih[4], il[4];
                ldsm_x4(rh[0], rh[1], rh[2], rh[3], kRH + offB);
                ldsm_x4(rl[0], rl[1], rl[2], rl[3], kRL + offB);
                ldsm_x4(ih[0], ih[1], ih[2], ih[3], kIH + offB);
                ldsm_x4(il[0], il[1], il[2], il[3], kIL + offB);
                mma_bf16(sacc[2 * g],     arh, rh[0], rh[1]);
                mma_bf16(sacc[2 * g],     arl, rh[0], rh[1]);
                mma_bf16(sacc[2 * g],     arh, rl[0], rl[1]);
                mma_bf16(sacc[2 * g],     aih, ih[0], ih[1]);
                mma_bf16(sacc[2 * g],     ail, ih[0], ih[1]);
                mma_bf16(sacc[2 * g],     aih, il[0], il[1]);
                mma_bf16(sacc[2 * g + 1], arh, rh[2], rh[3]);
                mma_bf16(sacc[2 * g + 1], arl, rh[2], rh[3]);
                mma_bf16(sacc[2 * g + 1], arh, rl[2], rl[3]);
                mma_bf16(sacc[2 * g + 1], aih, ih[2], ih[3]);
                mma_bf16(sacc[2 * g + 1], ail, ih[2], ih[3]);
                mma_bf16(sacc[2 * g + 1], aih, il[2], il[3]);
            }
        }

        // ---- gate + scale + mask + streaming softmax ----
        float pm0 = -INFINITY, pm1 = -INFINITY;
#pragma unroll
        for (int f = 0; f < 8; f++) {
            const int sb2 = s0 + f * 8 + (lane & 3) * 2;
            const float2 gs0 = g_gate[h * SEQ + sb2];
            const float2 gs1 = g_gate[h * SEQ + sb2 + 1];
            float v00 = sacc[f][0] * SCALE_F * (gs0.x * gt0.x + gs0.y * gt0.y);
            float v01 = sacc[f][1] * SCALE_F * (gs1.x * gt0.x + gs1.y * gt0.y);
            float v10 = sacc[f][2] * SCALE_F * (gs0.x * gt1.x + gs0.y * gt1.y);
            float v11 = sacc[f][3] * SCALE_F * (gs1.x * gt1.x + gs1.y * gt1.y);
            if (sb2 > t0g)     v00 = -INFINITY;
            if (sb2 + 1 > t0g) v01 = -INFINITY;
            if (sb2 > t1g)     v10 = -INFINITY;
            if (sb2 + 1 > t1g) v11 = -INFINITY;
            sacc[f][0] = v00; sacc[f][1] = v01; sacc[f][2] = v10; sacc[f][3] = v11;
            pm0 = fmaxf(pm0, fmaxf(v00, v01));
            pm1 = fmaxf(pm1, fmaxf(v10, v11));
        }
        pm0 = fmaxf(pm0, __shfl_xor_sync(0xffffffffu, pm0, 1));
        pm0 = fmaxf(pm0, __shfl_xor_sync(0xffffffffu, pm0, 2));
        pm1 = fmaxf(pm1, __shfl_xor_sync(0xffffffffu, pm1, 1));
        pm1 = fmaxf(pm1, __shfl_xor_sync(0xffffffffu, pm1, 2));

        const float mn0 = fmaxf(m0, pm0), mn1 = fmaxf(m1, pm1);
        const float cr0 = __expf(m0 - mn0), cr1 = __expf(m1 - mn1);
        float rs0 = 0.f, rs1 = 0.f;
#pragma unroll
        for (int f = 0; f < 8; f++) {
            sacc[f][0] = __expf(sacc[f][0] - mn0);
            sacc[f][1] = __expf(sacc[f][1] - mn0);
            sacc[f][2] = __expf(sacc[f][2] - mn1);
            sacc[f][3] = __expf(sacc[f][3] - mn1);
            rs0 += sacc[f][0] + sacc[f][1];
            rs1 += sacc[f][2] + sacc[f][3];
        }
        rs0 += __shfl_xor_sync(0xffffffffu, rs0, 1);
        rs0 += __shfl_xor_sync(0xffffffffu, rs0, 2);
        rs1 += __shfl_xor_sync(0xffffffffu, rs1, 1);
        rs1 += __shfl_xor_sync(0xffffffffu, rs1, 2);
        l0 = l0 * cr0 + rs0; m0 = mn0;
        l1 = l1 * cr1 + rs1; m1 = mn1;
#pragma unroll
        for (int f = 0; f < 8; f++) {
            oacc[f][0] *= cr0; oacc[f][1] *= cr0;
            oacc[f][2] *= cr1; oacc[f][3] *= cr1;
        }

        // ---- O += P @ V (split-bf16, acc-layout == A-layout repack) ----
#pragma unroll
        for (int j = 0; j < 4; j++) {
            // A frags hi/lo from acc frags 2j, 2j+1
            float p00 = sacc[2 * j][0],     p01 = sacc[2 * j][1];
            float p02 = sacc[2 * j][2],     p03 = sacc[2 * j][3];
            float p10 = sacc[2 * j + 1][0], p11 = sacc[2 * j + 1][1];
            float p12 = sacc[2 * j + 1][2], p13 = sacc[2 * j + 1][3];
            float h00 = __bfloat162float(__float2bfloat16(p00));
            float h01 = __bfloat162float(__float2bfloat16(p01));
            float h02 = __bfloat162float(__float2bfloat16(p02));
            float h03 = __bfloat162float(__float2bfloat16(p03));
            float h10 = __bfloat162float(__float2bfloat16(p10));
            float h11 = __bfloat162float(__float2bfloat16(p11));
            float h12 = __bfloat162float(__float2bfloat16(p12));
            float h13 = __bfloat162float(__float2bfloat16(p13));
            uint32_t ph[4] = {pack_bf16(h00, h01), pack_bf16(h02, h03),
                              pack_bf16(h10, h11), pack_bf16(h12, h13)};
            uint32_t pl[4] = {pack_bf16(p00 - h00, p01 - h01), pack_bf16(p02 - h02, p03 - h03),
                              pack_bf16(p10 - h10, p11 - h11), pack_bf16(p12 - h12, p13 - h13)};
#pragma unroll
            for (int dg = 0; dg < 4; dg++) {
                const uint32_t offV = SWZ128((uint32_t)((16 * j + a_row) * 128) +
                                             (uint32_t)(dg * 32) + a_cb);
                uint32_t vh[4], vl[4];
                ldsm_x4_t(vh[0], vh[1], vh[2], vh[3], vH + offV);
                ldsm_x4_t(vl[0], vl[1], vl[2], vl[3], vL + offV);
                mma_bf16(oacc[2 * dg],     ph, vh[0], vh[1]);
                mma_bf16(oacc[2 * dg],     pl, vh[0], vh[1]);
                mma_bf16(oacc[2 * dg],     ph, vl[0], vl[1]);
                mma_bf16(oacc[2 * dg + 1], ph, vh[2], vh[3]);
                mma_bf16(oacc[2 * dg + 1], pl, vh[2], vh[3]);
                mma_bf16(oacc[2 * dg + 1], ph, vl[2], vl[3]);
            }
        }
        __syncthreads();
    }

    // epilogue: normalize, write bf16 hi/lo directly
    const float iv0 = 1.0f / l0, iv1 = 1.0f / l1;
    const size_t row0 = (size_t)(b * SEQ + t0g) * CDIM + h * HDIM;
    const size_t row1 = (size_t)(b * SEQ + t1g) * CDIM + h * HDIM;
#pragma unroll
    for (int f = 0; f < 8; f++) {
        const int d = f * 8 + (lane & 3) * 2;
        float o00 = oacc[f][0] * iv0, o01 = oacc[f][1] * iv0;
        float o10 = oacc[f][2] * iv1, o11 = oacc[f][3] * iv1;
        float h00 = __bfloat162float(__float2bfloat16(o00));
        float h01 = __bfloat162float(__float2bfloat16(o01));
        float h10 = __bfloat162float(__float2bfloat16(o10));
        float h11 = __bfloat162float(__float2bfloat16(o11));
        *(uint32_t*)&g_ah[row0 + d] = pack_bf16(h00, h01);
        *(uint32_t*)&g_al[row0 + d] = pack_bf16(o00 - h00, o01 - h01);
        *(uint32_t*)&g_ah[row1 + d] = pack_bf16(h10, h11);
        *(uint32_t*)&g_al[row1 + d] = pack_bf16(o10 - h10, o11 - h11);
    }
}

// ---------------- launch ---------------------------------------------------
extern "C" void kernel_launch(void* const* d_in, const int* in_sizes, int n_in,
                              void* d_out, int out_size) {
    const float* x     = (const float*)d_in[0];
    const float* Wq    = (const float*)d_in[1];
    const float* Wk    = (const float*)d_in[2];
    const float* Wv    = (const float*)d_in[3];
    const float* Wo    = (const float*)d_in[4];
    const float* theta = (const float*)d_in[5];
    float* out = (float*)d_out;

    float *qraw, *kraw, *v;
    __nv_bfloat16 *xh, *xl, *ah, *al, *vh, *vl;
    __nv_bfloat16 *wqh, *wql, *wkh, *wkl, *wvh, *wvl, *woh, *wol;
    cudaGetSymbolAddress((void**)&qraw, g_qraw);
    cudaGetSymbolAddress((void**)&kraw, g_kraw);
    cudaGetSymbolAddress((void**)&v,    g_v);
    cudaGetSymbolAddress((void**)&xh,  g_xh);
    cudaGetSymbolAddress((void**)&xl,  g_xl);
    cudaGetSymbolAddress((void**)&ah,  g_ah);
    cudaGetSymbolAddress((void**)&al,  g_al);
    cudaGetSymbolAddress((void**)&vh,  g_vh);
    cudaGetSymbolAddress((void**)&vl,  g_vl);
    cudaGetSymbolAddress((void**)&wqh, g_wqh);
    cudaGetSymbolAddress((void**)&wql, g_wql);
    cudaGetSymbolAddress((void**)&wkh, g_wkh);
    cudaGetSymbolAddress((void**)&wkl, g_wkl);
    cudaGetSymbolAddress((void**)&wvh, g_wvh);
    cudaGetSymbolAddress((void**)&wvl, g_wvl);
    cudaGetSymbolAddress((void**)&woh, g_woh);
    cudaGetSymbolAddress((void**)&wol, g_wol);

    cudaFuncSetAttribute(gemm_bf16x3,
                         cudaFuncAttributeMaxDynamicSharedMemorySize, GEMM_SMEM);
    cudaFuncSetAttribute(attn_mma,
                         cudaFuncAttributeMaxDynamicSharedMemorySize, ATT_SMEM);

    dim3 tblk(32, 8);
    transpose_split<<<dim3(2 * CDIM / 32, CDIM / 32), tblk>>>(Wq, wqh, wql, CDIM, 2 * CDIM);
    transpose_split<<<dim3(2 * CDIM / 32, CDIM / 32), tblk>>>(Wk, wkh, wkl, CDIM, 2 * CDIM);
    transpose_split<<<dim3(CDIM / 32, CDIM / 32), tblk>>>(Wv, wvh, wvl, CDIM, CDIM);
    transpose_split<<<dim3(CDIM / 32, CDIM / 32), tblk>>>(Wo, woh, wol, CDIM, CDIM);

    convert_split<<<MROWS * CDIM / 4 / 256, 256>>>(x, xh, xl);
    gate_init<<<HEADS * SEQ / 256, 256>>>(theta);

    gemm_bf16x3<<<dim3(2 * CDIM / 128, MROWS / 128), 256, GEMM_SMEM>>>(xh, xl, wqh, wql, qraw, 2 * CDIM);
    gemm_bf16x3<<<dim3(2 * CDIM / 128, MROWS / 128), 256, GEMM_SMEM>>>(xh, xl, wkh, wkl, kraw, 2 * CDIM);
    gemm_bf16x3<<<dim3(CDIM / 128, MROWS / 128), 256, GEMM_SMEM>>>(xh, xl, wvh, wvl, v, CDIM);

    transform_qk_bf16<<<MROWS * CDIM / 2 / 256, 256>>>();
    convert_split<<<MROWS * CDIM / 4 / 256, 256>>>(v, vh, vl);

    attn_mma<<<dim3(SEQ / AQT, HEADS, BATCH), 256, ATT_SMEM>>>();

    gemm_bf16x3<<<dim3(CDIM / 128, MROWS / 128), 256, GEMM_SMEM>>>(ah, al, woh, wol, out, CDIM);
}

// round 5
// speedup vs baseline: 3.2789x; 1.5715x over previous
#include <cuda_runtime.h>
#include <cuda_bf16.h>
#include <cstdint>
#include <math.h>

// Problem constants
#define BATCH   2
#define SEQ     2048
#define CDIM    1024
#define HEADS   16
#define HDIM    64
#define GAMMA_F 8.0f
#define SCALE_F 0.125f
#define MROWS   (BATCH*SEQ)          // 4096
#define KDIM    1024

// ---------------- scratch (device globals; no allocation allowed) ----------
__device__ float g_qraw[MROWS * 2 * CDIM];
__device__ float g_kraw[MROWS * 2 * CDIM];
__device__ float g_v   [MROWS * CDIM];

// split-bf16 operands
__device__ __nv_bfloat16 g_xh [MROWS * CDIM];
__device__ __nv_bfloat16 g_xl [MROWS * CDIM];
__device__ __nv_bfloat16 g_ah [MROWS * CDIM];
__device__ __nv_bfloat16 g_al [MROWS * CDIM];
__device__ __nv_bfloat16 g_wqh[2 * CDIM * CDIM];
__device__ __nv_bfloat16 g_wql[2 * CDIM * CDIM];
__device__ __nv_bfloat16 g_wkh[2 * CDIM * CDIM];
__device__ __nv_bfloat16 g_wkl[2 * CDIM * CDIM];
__device__ __nv_bfloat16 g_wvh[CDIM * CDIM];
__device__ __nv_bfloat16 g_wvl[CDIM * CDIM];
__device__ __nv_bfloat16 g_woh[CDIM * CDIM];
__device__ __nv_bfloat16 g_wol[CDIM * CDIM];

// attention operands, split bf16
__device__ __nv_bfloat16 g_qrh[MROWS * CDIM];
__device__ __nv_bfloat16 g_qrl[MROWS * CDIM];
__device__ __nv_bfloat16 g_qih[MROWS * CDIM];
__device__ __nv_bfloat16 g_qil[MROWS * CDIM];
__device__ __nv_bfloat16 g_krh[MROWS * CDIM];
__device__ __nv_bfloat16 g_krl[MROWS * CDIM];
__device__ __nv_bfloat16 g_kih[MROWS * CDIM];
__device__ __nv_bfloat16 g_kil[MROWS * CDIM];
__device__ __nv_bfloat16 g_vh [MROWS * CDIM];
__device__ __nv_bfloat16 g_vl [MROWS * CDIM];
__device__ float2 g_gate[HEADS * SEQ];

// ---------------- helpers ---------------------------------------------------
__device__ __forceinline__ uint32_t smem_u32(const void* p) {
    uint32_t a;
    asm("{ .reg .u64 t; cvta.to.shared.u64 t, %1; cvt.u32.u64 %0, t; }"
        : "=r"(a) : "l"(p));
    return a;
}
#define SWZ128(o) ((o) ^ (((o) >> 3) & 0x70))

__device__ __forceinline__ void cp_async16(uint32_t dst, const void* src) {
    asm volatile("cp.async.cg.shared.global [%0], [%1], 16;" :: "r"(dst), "l"(src));
}

__device__ __forceinline__ void ldsm_x4(uint32_t& r0, uint32_t& r1,
                                        uint32_t& r2, uint32_t& r3, uint32_t addr) {
    asm volatile("ldmatrix.sync.aligned.m8n8.x4.shared.b16 {%0,%1,%2,%3}, [%4];"
                 : "=r"(r0), "=r"(r1), "=r"(r2), "=r"(r3) : "r"(addr));
}
__device__ __forceinline__ void ldsm_x4_t(uint32_t& r0, uint32_t& r1,
                                          uint32_t& r2, uint32_t& r3, uint32_t addr) {
    asm volatile("ldmatrix.sync.aligned.m8n8.x4.trans.shared.b16 {%0,%1,%2,%3}, [%4];"
                 : "=r"(r0), "=r"(r1), "=r"(r2), "=r"(r3) : "r"(addr));
}

__device__ __forceinline__ void mma_bf16(float* c, const uint32_t* a,
                                         uint32_t b0, uint32_t b1) {
    asm volatile(
        "mma.sync.aligned.m16n8k16.row.col.f32.bf16.bf16.f32 "
        "{%0,%1,%2,%3}, {%4,%5,%6,%7}, {%8,%9}, {%0,%1,%2,%3};"
        : "+f"(c[0]), "+f"(c[1]), "+f"(c[2]), "+f"(c[3])
        : "r"(a[0]), "r"(a[1]), "r"(a[2]), "r"(a[3]), "r"(b0), "r"(b1));
}

__device__ __forceinline__ uint32_t pack_bf16(float a, float b) {
    __nv_bfloat162 t = __float22bfloat162_rn(make_float2(a, b));  // a -> low
    return *reinterpret_cast<uint32_t*>(&t);
}

// ---------------- split-bf16 GEMM: C[M,N] = A[M,K] * B[N,K]^T ---------------
// Block tile 128x256, 8 warps (2x4) of 64x64. K-chunk 64, 2-stage cp.async.
// 96 MMAs per 16 ldmatrix per warp per k16 step (6:1 density).
#define BK       64
#define NCH      (KDIM / BK)             // 16
#define A_TB     16384                   // 128 rows * 128B
#define B_TB     32768                   // 256 rows * 128B
#define STG_B    (2 * A_TB + 2 * B_TB)   // 98304
#define GEMM_SMEM (2 * STG_B)            // 196608

__global__ __launch_bounds__(256, 1)
void gemm_bf16x3(const __nv_bfloat16* __restrict__ Ah, const __nv_bfloat16* __restrict__ Al,
                 const __nv_bfloat16* __restrict__ Bh, const __nv_bfloat16* __restrict__ Bl,
                 float* __restrict__ Cm, int N) {
    extern __shared__ char smem[];
    const uint32_t sb = smem_u32(smem);
    const int tid = threadIdx.x, wid = tid >> 5, lane = tid & 31;
    const int m0 = blockIdx.y * 128, n0 = blockIdx.x * 256;
    const int wm = (wid & 1) * 64;
    const int wn = (wid >> 1) * 64;

    const __nv_bfloat16* gAh = Ah + (size_t)m0 * KDIM;
    const __nv_bfloat16* gAl = Al + (size_t)m0 * KDIM;
    const __nv_bfloat16* gBh = Bh + (size_t)n0 * KDIM;
    const __nv_bfloat16* gBl = Bl + (size_t)n0 * KDIM;

    float acc[4][8][4];
#pragma unroll
    for (int i = 0; i < 4; i++)
#pragma unroll
        for (int j = 0; j < 8; j++)
#pragma unroll
            for (int e = 0; e < 4; e++) acc[i][j][e] = 0.f;

    const int a_row = (lane & 15);
    const uint32_t a_cb = (uint32_t)((lane >> 4) * 16);
    const int b_row = ((lane >> 4) & 1) * 8 + (lane & 7);
    const uint32_t b_cb = (uint32_t)(((lane >> 3) & 1) * 16);

    // stage loader: A (hi,lo) 128 rows + B (hi,lo) 256 rows, K-chunk 64
    auto load_stage = [&](uint32_t st, int kc) {
#pragma unroll
        for (int it = 0; it < 4; it++) {
            int idx = tid + it * 256;
            int r = idx >> 3, u = idx & 7;
            uint32_t off = SWZ128((uint32_t)(r * 128 + u * 16));
            cp_async16(st + off,        gAh + (size_t)r * KDIM + kc + u * 8);
            cp_async16(st + A_TB + off, gAl + (size_t)r * KDIM + kc + u * 8);
        }
#pragma unroll
        for (int it = 0; it < 8; it++) {
            int idx = tid + it * 256;
            int r = idx >> 3, u = idx & 7;
            uint32_t off = SWZ128((uint32_t)(r * 128 + u * 16));
            cp_async16(st + 2 * A_TB + off,        gBh + (size_t)r * KDIM + kc + u * 8);
            cp_async16(st + 2 * A_TB + B_TB + off, gBl + (size_t)r * KDIM + kc + u * 8);
        }
    };

    load_stage(sb, 0);
    asm volatile("cp.async.commit_group;");

    for (int i = 0; i < NCH; i++) {
        if (i + 1 < NCH) {
            load_stage(sb + ((i + 1) & 1) * STG_B, (i + 1) * BK);
            asm volatile("cp.async.commit_group;");
            asm volatile("cp.async.wait_group 1;" ::: "memory");
        } else {
            asm volatile("cp.async.wait_group 0;" ::: "memory");
        }
        __syncthreads();

        const uint32_t st = sb + (i & 1) * STG_B;
        const uint32_t aH = st, aL = st + A_TB;
        const uint32_t bH = st + 2 * A_TB, bL = st + 2 * A_TB + B_TB;

#pragma unroll
        for (int ks = 0; ks < 4; ks++) {
            const uint32_t kb = (uint32_t)(ks * 32);
            uint32_t ah[4][4], al[4][4];
#pragma unroll
            for (int mi = 0; mi < 4; mi++) {
                uint32_t off = SWZ128((uint32_t)((wm + mi * 16 + a_row) * 128) + kb + a_cb);
                ldsm_x4(ah[mi][0], ah[mi][1], ah[mi][2], ah[mi][3], aH + off);
                ldsm_x4(al[mi][0], al[mi][1], al[mi][2], al[mi][3], aL + off);
            }
#pragma unroll
            for (int ng = 0; ng < 4; ng++) {
                uint32_t off = SWZ128((uint32_t)((wn + ng * 16 + b_row) * 128) + kb + b_cb);
                uint32_t bh[4], bl[4];
                ldsm_x4(bh[0], bh[1], bh[2], bh[3], bH + off);
                ldsm_x4(bl[0], bl[1], bl[2], bl[3], bL + off);
#pragma unroll
                for (int mi = 0; mi < 4; mi++) {
                    mma_bf16(acc[mi][2 * ng],     ah[mi], bh[0], bh[1]);
                    mma_bf16(acc[mi][2 * ng],     ah[mi], bl[0], bl[1]);
                    mma_bf16(acc[mi][2 * ng],     al[mi], bh[0], bh[1]);
                    mma_bf16(acc[mi][2 * ng + 1], ah[mi], bh[2], bh[3]);
                    mma_bf16(acc[mi][2 * ng + 1], ah[mi], bl[2], bl[3]);
                    mma_bf16(acc[mi][2 * ng + 1], al[mi], bh[2], bh[3]);
                }
            }
        }
        __syncthreads();
    }

    const int cr = lane >> 2;
    const int cc = (lane & 3) * 2;
#pragma unroll
    for (int mi = 0; mi < 4; mi++) {
#pragma unroll
        for (int nj = 0; nj < 8; nj++) {
            const int r = m0 + wm + mi * 16 + cr;
            const int c = n0 + wn + nj * 8 + cc;
            *(float2*)&Cm[(size_t)r * N + c] = make_float2(acc[mi][nj][0], acc[mi][nj][1]);
            *(float2*)&Cm[(size_t)(r + 8) * N + c] = make_float2(acc[mi][nj][2], acc[mi][nj][3]);
        }
    }
}

// ---------------- fp32 -> (hi,lo) bf16 split -------------------------------
__global__ __launch_bounds__(256)
void convert_split(const float* __restrict__ src, __nv_bfloat16* __restrict__ hi,
                   __nv_bfloat16* __restrict__ lo) {
    int i = blockIdx.x * 256 + threadIdx.x;
    float4 v = ((const float4*)src)[i];
    float f[4] = {v.x, v.y, v.z, v.w};
    __nv_bfloat16 h[4], l[4];
#pragma unroll
    for (int j = 0; j < 4; j++) {
        h[j] = __float2bfloat16(f[j]);
        l[j] = __float2bfloat16(f[j] - __bfloat162float(h[j]));
    }
    *(__nv_bfloat162*)(hi + 4 * (size_t)i)     = __nv_bfloat162(h[0], h[1]);
    *(__nv_bfloat162*)(hi + 4 * (size_t)i + 2) = __nv_bfloat162(h[2], h[3]);
    *(__nv_bfloat162*)(lo + 4 * (size_t)i)     = __nv_bfloat162(l[0], l[1]);
    *(__nv_bfloat162*)(lo + 4 * (size_t)i + 2) = __nv_bfloat162(l[2], l[3]);
}

// ---------------- weight transpose + split ---------------------------------
__global__ __launch_bounds__(256)
void transpose_split(const float* __restrict__ W, __nv_bfloat16* __restrict__ Hh,
                     __nv_bfloat16* __restrict__ Hl, int K, int N) {
    __shared__ float t[32][33];
    const int tx = threadIdx.x, ty = threadIdx.y;
    const int n0 = blockIdx.x * 32, k0 = blockIdx.y * 32;
#pragma unroll
    for (int i = 0; i < 32; i += 8)
        t[ty + i][tx] = W[(size_t)(k0 + ty + i) * N + n0 + tx];
    __syncthreads();
#pragma unroll
    for (int i = 0; i < 32; i += 8) {
        float v = t[tx][ty + i];
        __nv_bfloat16 h = __float2bfloat16(v);
        Hh[(size_t)(n0 + ty + i) * K + k0 + tx] = h;
        Hl[(size_t)(n0 + ty + i) * K + k0 + tx] =
            __float2bfloat16(v - __bfloat162float(h));
    }
}

// ---------------- amp/phase transform -> split bf16 -------------------------
__device__ __forceinline__ float softplus_f(float a) {
    return (a > 20.f) ? a : log1pf(expf(a));
}
__device__ __forceinline__ void split2(float a, float b, __nv_bfloat16* H,
                                       __nv_bfloat16* L, size_t idx) {
    __nv_bfloat16 ha = __float2bfloat16(a), hb = __float2bfloat16(b);
    *(__nv_bfloat162*)(H + idx) = __nv_bfloat162(ha, hb);
    *(__nv_bfloat162*)(L + idx) = __nv_bfloat162(
        __float2bfloat16(a - __bfloat162float(ha)),
        __float2bfloat16(b - __bfloat162float(hb)));
}

__global__ __launch_bounds__(256)
void transform_qk_bf16() {
    int i2 = blockIdx.x * 256 + threadIdx.x;
    int c2 = i2 * 2;
    int bt = c2 >> 10;
    int c  = c2 & 1023;
    size_t rbase = (size_t)bt * (2 * CDIM);
    size_t oidx  = (size_t)bt * CDIM + c;

    float qa0 = g_qraw[rbase + c],        qa1 = g_qraw[rbase + c + 1];
    float qp0 = g_qraw[rbase + CDIM + c], qp1 = g_qraw[rbase + CDIM + c + 1];
    float ka0 = g_kraw[rbase + c],        ka1 = g_kraw[rbase + c + 1];
    float kp0 = g_kraw[rbase + CDIM + c], kp1 = g_kraw[rbase + CDIM + c + 1];

    float qs0 = softplus_f(qa0), qs1 = softplus_f(qa1);
    float ks0 = softplus_f(ka0), ks1 = softplus_f(ka1);
    float s0, c0, s1, c1, s2, c2f, s3, c3;
    sincosf(qp0, &s0, &c0); sincosf(qp1, &s1, &c1);
    sincosf(kp0, &s2, &c2f); sincosf(kp1, &s3, &c3);

    split2(qs0 * c0, qs1 * c1, g_qrh, g_qrl, oidx);
    split2(qs0 * s0, qs1 * s1, g_qih, g_qil, oidx);
    split2(ks0 * c2f, ks1 * c3, g_krh, g_krl, oidx);
    split2(ks0 * s2, ks1 * s3, g_kih, g_kil, oidx);
}

__global__ void gate_init(const float* __restrict__ theta) {
    int i = blockIdx.x * 256 + threadIdx.x;
    int h = i >> 11, s = i & (SEQ - 1);
    float th = theta[h] * (1.0f / GAMMA_F);
    float sn, cs;
    sincosf(th * (float)s, &sn, &cs);
    g_gate[i] = make_float2(cs, sn);
}

// ---------------- tensor-core flash attention with moiré gate ---------------
#define AQT 128
#define AST 64
#define AQ_TILE 16384
#define AKV_TILE 8192
#define AKV_BUF (6 * AKV_TILE)
#define ATT_SMEM (4 * AQ_TILE + 2 * AKV_BUF)

__global__ __launch_bounds__(256)
void attn_mma() {
    extern __shared__ char smem[];
    const uint32_t sQ  = smem_u32(smem);
    const uint32_t sKV = sQ + 4 * AQ_TILE;

    const int tid = threadIdx.x, w = tid >> 5, lane = tid & 31;
    const int q0 = (int)(gridDim.x - 1 - blockIdx.x) * AQT;
    const int h = blockIdx.y, b = blockIdx.z;

    const __nv_bfloat16* qs[4]  = {g_qrh, g_qrl, g_qih, g_qil};
    const __nv_bfloat16* kvs[6] = {g_krh, g_krl, g_kih, g_kil, g_vh, g_vl};

    const int a_row = lane & 15;
    const uint32_t a_cb = (uint32_t)((lane >> 4) * 16);
    const int b_row = ((lane >> 4) & 1) * 8 + (lane & 7);
    const uint32_t b_cb = (uint32_t)(((lane >> 3) & 1) * 16);

#pragma unroll
    for (int it = 0; it < 16; it++) {
        int idx = tid + it * 256;
        int tile = idx >> 10, rr = (idx >> 3) & 127, u = idx & 7;
        cp_async16(sQ + tile * AQ_TILE + SWZ128((uint32_t)(rr * 128 + u * 16)),
                   qs[tile] + ((size_t)(b * SEQ + q0 + rr) * CDIM + h * HDIM + u * 8));
    }
    asm volatile("cp.async.commit_group;");

    const int nS = q0 / AST + 2;

#pragma unroll
    for (int it = 0; it < 12; it++) {
        int idx = tid + it * 256;
        int tile = idx >> 9, rr = (idx >> 3) & 63, u = idx & 7;
        cp_async16(sKV + tile * AKV_TILE + SWZ128((uint32_t)(rr * 128 + u * 16)),
                   kvs[tile] + ((size_t)(b * SEQ + rr) * CDIM + h * HDIM + u * 8));
    }
    asm volatile("cp.async.commit_group;");

    const int t0g = q0 + w * 16 + (lane >> 2);
    const int t1g = t0g + 8;
    const float2 gt0 = g_gate[h * SEQ + t0g];
    const float2 gt1 = g_gate[h * SEQ + t1g];

    float m0 = -INFINITY, m1 = -INFINITY, l0 = 0.f, l1 = 0.f;
    float oacc[8][4];
#pragma unroll
    for (int f = 0; f < 8; f++)
#pragma unroll
        for (int e = 0; e < 4; e++) oacc[f][e] = 0.f;

    for (int i = 0; i < nS; i++) {
        if (i + 1 < nS) {
            const int s0n = (i + 1) * AST;
            const uint32_t nb = sKV + ((i + 1) & 1) * AKV_BUF;
#pragma unroll
            for (int it = 0; it < 12; it++) {
                int idx = tid + it * 256;
                int tile = idx >> 9, rr = (idx >> 3) & 63, u = idx & 7;
                cp_async16(nb + tile * AKV_TILE + SWZ128((uint32_t)(rr * 128 + u * 16)),
                           kvs[tile] + ((size_t)(b * SEQ + s0n + rr) * CDIM + h * HDIM + u * 8));
            }
            asm volatile("cp.async.commit_group;");
            asm volatile("cp.async.wait_group 1;" ::: "memory");
        } else {
            asm volatile("cp.async.wait_group 0;" ::: "memory");
        }
        __syncthreads();

        const int s0 = i * AST;
        const uint32_t kb0 = sKV + (i & 1) * AKV_BUF;
        const uint32_t kRH = kb0, kRL = kb0 + AKV_TILE;
        const uint32_t kIH = kb0 + 2 * AKV_TILE, kIL = kb0 + 3 * AKV_TILE;
        const uint32_t vH = kb0 + 4 * AKV_TILE, vL = kb0 + 5 * AKV_TILE;

        float sacc[8][4];
#pragma unroll
        for (int f = 0; f < 8; f++)
#pragma unroll
            for (int e = 0; e < 4; e++) sacc[f][e] = 0.f;

#pragma unroll
        for (int jd = 0; jd < 4; jd++) {
            const uint32_t kb = (uint32_t)(jd * 32);
            const uint32_t offA = SWZ128((uint32_t)((w * 16 + a_row) * 128) + kb + a_cb);
            uint32_t arh[4], arl[4], aih[4], ail[4];
            ldsm_x4(arh[0], arh[1], arh[2], arh[3], sQ + offA);
            ldsm_x4(arl[0], arl[1], arl[2], arl[3], sQ + AQ_TILE + offA);
            ldsm_x4(aih[0], aih[1], aih[2], aih[3], sQ + 2 * AQ_TILE + offA);
            ldsm_x4(ail[0], ail[1], ail[2], ail[3], sQ + 3 * AQ_TILE + offA);
#pragma unroll
            for (int g = 0; g < 4; g++) {
                const uint32_t offB = SWZ128((uint32_t)((g * 16 + b_row) * 128) + kb + b_cb);
                uint32_t rh[4], rl[4], ih[4], il[4];
                ldsm_x4(rh[0], rh[1], rh[2], rh[3], kRH + offB);
                ldsm_x4(rl[0], rl[1], rl[2], rl[3], kRL + offB);
                ldsm_x4(ih[0], ih[1], ih[2], ih[3], kIH + offB);
                ldsm_x4(il[0], il[1], il[2], il[3], kIL + offB);
                mma_bf16(sacc[2 * g],     arh, rh[0], rh[1]);
                mma_bf16(sacc[2 * g],     arl, rh[0], rh[1]);
                mma_bf16(sacc[2 * g],     arh, rl[0], rl[1]);
                mma_bf16(sacc[2 * g],     aih, ih[0], ih[1]);
                mma_bf16(sacc[2 * g],     ail, ih[0], ih[1]);
                mma_bf16(sacc[2 * g],     aih, il[0], il[1]);
                mma_bf16(sacc[2 * g + 1], arh, rh[2], rh[3]);
                mma_bf16(sacc[2 * g + 1], arl, rh[2], rh[3]);
                mma_bf16(sacc[2 * g + 1], arh, rl[2], rl[3]);
                mma_bf16(sacc[2 * g + 1], aih, ih[2], ih[3]);
                mma_bf16(sacc[2 * g + 1], ail, ih[2], ih[3]);
                mma_bf16(sacc[2 * g + 1], aih, il[2], il[3]);
            }
        }

        float pm0 = -INFINITY, pm1 = -INFINITY;
#pragma unroll
        for (int f = 0; f < 8; f++) {
            const int sb2 = s0 + f * 8 + (lane & 3) * 2;
            const float2 gs0 = g_gate[h * SEQ + sb2];
            const float2 gs1 = g_gate[h * SEQ + sb2 + 1];
            float v00 = sacc[f][0] * SCALE_F * (gs0.x * gt0.x + gs0.y * gt0.y);
            float v01 = sacc[f][1] * SCALE_F * (gs1.x * gt0.x + gs1.y * gt0.y);
            float v10 = sacc[f][2] * SCALE_F * (gs0.x * gt1.x + gs0.y * gt1.y);
            float v11 = sacc[f][3] * SCALE_F * (gs1.x * gt1.x + gs1.y * gt1.y);
            if (sb2 > t0g)     v00 = -INFINITY;
            if (sb2 + 1 > t0g) v01 = -INFINITY;
            if (sb2 > t1g)     v10 = -INFINITY;
            if (sb2 + 1 > t1g) v11 = -INFINITY;
            sacc[f][0] = v00; sacc[f][1] = v01; sacc[f][2] = v10; sacc[f][3] = v11;
            pm0 = fmaxf(pm0, fmaxf(v00, v01));
            pm1 = fmaxf(pm1, fmaxf(v10, v11));
        }
        pm0 = fmaxf(pm0, __shfl_xor_sync(0xffffffffu, pm0, 1));
        pm0 = fmaxf(pm0, __shfl_xor_sync(0xffffffffu, pm0, 2));
        pm1 = fmaxf(pm1, __shfl_xor_sync(0xffffffffu, pm1, 1));
        pm1 = fmaxf(pm1, __shfl_xor_sync(0xffffffffu, pm1, 2));

        const float mn0 = fmaxf(m0, pm0), mn1 = fmaxf(m1, pm1);
        const float cr0 = __expf(m0 - mn0), cr1 = __expf(m1 - mn1);
        float rs0 = 0.f, rs1 = 0.f;
#pragma unroll
        for (int f = 0; f < 8; f++) {
            sacc[f][0] = __expf(sacc[f][0] - mn0);
            sacc[f][1] = __expf(sacc[f][1] - mn0);
            sacc[f][2] = __expf(sacc[f][2] - mn1);
            sacc[f][3] = __expf(sacc[f][3] - mn1);
            rs0 += sacc[f][0] + sacc[f][1];
            rs1 += sacc[f][2] + sacc[f][3];
        }
        rs0 += __shfl_xor_sync(0xffffffffu, rs0, 1);
        rs0 += __shfl_xor_sync(0xffffffffu, rs0, 2);
        rs1 += __shfl_xor_sync(0xffffffffu, rs1, 1);
        rs1 += __shfl_xor_sync(0xffffffffu, rs1, 2);
        l0 = l0 * cr0 + rs0; m0 = mn0;
        l1 = l1 * cr1 + rs1; m1 = mn1;
#pragma unroll
        for (int f = 0; f < 8; f++) {
            oacc[f][0] *= cr0; oacc[f][1] *= cr0;
            oacc[f][2] *= cr1; oacc[f][3] *= cr1;
        }

#pragma unroll
        for (int j = 0; j < 4; j++) {
            float p00 = sacc[2 * j][0],     p01 = sacc[2 * j][1];
            float p02 = sacc[2 * j][2],     p03 = sacc[2 * j][3];
            float p10 = sacc[2 * j + 1][0], p11 = sacc[2 * j + 1][1];
            float p12 = sacc[2 * j + 1][2], p13 = sacc[2 * j + 1][3];
            float h00 = __bfloat162float(__float2bfloat16(p00));
            float h01 = __bfloat162float(__float2bfloat16(p01));
            float h02 = __bfloat162float(__float2bfloat16(p02));
            float h03 = __bfloat162float(__float2bfloat16(p03));
            float h10 = __bfloat162float(__float2bfloat16(p10));
            float h11 = __bfloat162float(__float2bfloat16(p11));
            float h12 = __bfloat162float(__float2bfloat16(p12));
            float h13 = __bfloat162float(__float2bfloat16(p13));
            uint32_t ph[4] = {pack_bf16(h00, h01), pack_bf16(h02, h03),
                              pack_bf16(h10, h11), pack_bf16(h12, h13)};
            uint32_t pl[4] = {pack_bf16(p00 - h00, p01 - h01), pack_bf16(p02 - h02, p03 - h03),
                              pack_bf16(p10 - h10, p11 - h11), pack_bf16(p12 - h12, p13 - h13)};
#pragma unroll
            for (int dg = 0; dg < 4; dg++) {
                const uint32_t offV = SWZ128((uint32_t)((16 * j + a_row) * 128) +
                                             (uint32_t)(dg * 32) + a_cb);
                uint32_t vh[4], vl[4];
                ldsm_x4_t(vh[0], vh[1], vh[2], vh[3], vH + offV);
                ldsm_x4_t(vl[0], vl[1], vl[2], vl[3], vL + offV);
                mma_bf16(oacc[2 * dg],     ph, vh[0], vh[1]);
                mma_bf16(oacc[2 * dg],     pl, vh[0], vh[1]);
                mma_bf16(oacc[2 * dg],     ph, vl[0], vl[1]);
                mma_bf16(oacc[2 * dg + 1], ph, vh[2], vh[3]);
                mma_bf16(oacc[2 * dg + 1], pl, vh[2], vh[3]);
                mma_bf16(oacc[2 * dg + 1], ph, vl[2], vl[3]);
            }
        }
        __syncthreads();
    }

    const float iv0 = 1.0f / l0, iv1 = 1.0f / l1;
    const size_t row0 = (size_t)(b * SEQ + t0g) * CDIM + h * HDIM;
    const size_t row1 = (size_t)(b * SEQ + t1g) * CDIM + h * HDIM;
#pragma unroll
    for (int f = 0; f < 8; f++) {
        const int d = f * 8 + (lane & 3) * 2;
        float o00 = oacc[f][0] * iv0, o01 = oacc[f][1] * iv0;
        float o10 = oacc[f][2] * iv1, o11 = oacc[f][3] * iv1;
        float h00 = __bfloat162float(__float2bfloat16(o00));
        float h01 = __bfloat162float(__float2bfloat16(o01));
        float h10 = __bfloat162float(__float2bfloat16(o10));
        float h11 = __bfloat162float(__float2bfloat16(o11));
        *(uint32_t*)&g_ah[row0 + d] = pack_bf16(h00, h01);
        *(uint32_t*)&g_al[row0 + d] = pack_bf16(o00 - h00, o01 - h01);
        *(uint32_t*)&g_ah[row1 + d] = pack_bf16(h10, h11);
        *(uint32_t*)&g_al[row1 + d] = pack_bf16(o10 - h10, o11 - h11);
    }
}

// ---------------- launch ---------------------------------------------------
extern "C" void kernel_launch(void* const* d_in, const int* in_sizes, int n_in,
                              void* d_out, int out_size) {
    const float* x     = (const float*)d_in[0];
    const float* Wq    = (const float*)d_in[1];
    const float* Wk    = (const float*)d_in[2];
    const float* Wv    = (const float*)d_in[3];
    const float* Wo    = (const float*)d_in[4];
    const float* theta = (const float*)d_in[5];
    float* out = (float*)d_out;

    float *qraw, *kraw, *v;
    __nv_bfloat16 *xh, *xl, *ah, *al, *vh, *vl;
    __nv_bfloat16 *wqh, *wql, *wkh, *wkl, *wvh, *wvl, *woh, *wol;
    cudaGetSymbolAddress((void**)&qraw, g_qraw);
    cudaGetSymbolAddress((void**)&kraw, g_kraw);
    cudaGetSymbolAddress((void**)&v,    g_v);
    cudaGetSymbolAddress((void**)&xh,  g_xh);
    cudaGetSymbolAddress((void**)&xl,  g_xl);
    cudaGetSymbolAddress((void**)&ah,  g_ah);
    cudaGetSymbolAddress((void**)&al,  g_al);
    cudaGetSymbolAddress((void**)&vh,  g_vh);
    cudaGetSymbolAddress((void**)&vl,  g_vl);
    cudaGetSymbolAddress((void**)&wqh, g_wqh);
    cudaGetSymbolAddress((void**)&wql, g_wql);
    cudaGetSymbolAddress((void**)&wkh, g_wkh);
    cudaGetSymbolAddress((void**)&wkl, g_wkl);
    cudaGetSymbolAddress((void**)&wvh, g_wvh);
    cudaGetSymbolAddress((void**)&wvl, g_wvl);
    cudaGetSymbolAddress((void**)&woh, g_woh);
    cudaGetSymbolAddress((void**)&wol, g_wol);

    cudaFuncSetAttribute(gemm_bf16x3,
                         cudaFuncAttributeMaxDynamicSharedMemorySize, GEMM_SMEM);
    cudaFuncSetAttribute(attn_mma,
                         cudaFuncAttributeMaxDynamicSharedMemorySize, ATT_SMEM);

    dim3 tblk(32, 8);

    // order chosen so early profiled launches are GEMMs
    convert_split<<<MROWS * CDIM / 4 / 256, 256>>>(x, xh, xl);
    transpose_split<<<dim3(2 * CDIM / 32, CDIM / 32), tblk>>>(Wq, wqh, wql, CDIM, 2 * CDIM);
    gemm_bf16x3<<<dim3(2 * CDIM / 256, MROWS / 128), 256, GEMM_SMEM>>>(xh, xl, wqh, wql, qraw, 2 * CDIM);
    transpose_split<<<dim3(2 * CDIM / 32, CDIM / 32), tblk>>>(Wk, wkh, wkl, CDIM, 2 * CDIM);
    gemm_bf16x3<<<dim3(2 * CDIM / 256, MROWS / 128), 256, GEMM_SMEM>>>(xh, xl, wkh, wkl, kraw, 2 * CDIM);
    transpose_split<<<dim3(CDIM / 32, CDIM / 32), tblk>>>(Wv, wvh, wvl, CDIM, CDIM);
    gemm_bf16x3<<<dim3(CDIM / 256, MROWS / 128), 256, GEMM_SMEM>>>(xh, xl, wvh, wvl, v, CDIM);

    transform_qk_bf16<<<MROWS * CDIM / 2 / 256, 256>>>();
    convert_split<<<MROWS * CDIM / 4 / 256, 256>>>(v, vh, vl);
    gate_init<<<HEADS * SEQ / 256, 256>>>(theta);

    attn_mma<<<dim3(SEQ / AQT, HEADS, BATCH), 256, ATT_SMEM>>>();

    transpose_split<<<dim3(CDIM / 32, CDIM / 32), tblk>>>(Wo, woh, wol, CDIM, CDIM);
    gemm_bf16x3<<<dim3(CDIM / 256, MROWS / 128), 256, GEMM_SMEM>>>(ah, al, woh, wol, out, CDIM);
}

// round 6
// speedup vs baseline: 3.4988x; 1.0671x over previous
#include <cuda_runtime.h>
#include <cuda_bf16.h>
#include <cstdint>
#include <math.h>

// Problem constants
#define BATCH   2
#define SEQ     2048
#define CDIM    1024
#define HEADS   16
#define HDIM    64
#define GAMMA_F 8.0f
#define SCALE_F 0.125f
#define MROWS   (BATCH*SEQ)          // 4096
#define KDIM    1024

// ---------------- scratch (device globals; no allocation allowed) ----------
__device__ float g_qraw[MROWS * 2 * CDIM];
__device__ float g_kraw[MROWS * 2 * CDIM];
__device__ float g_v   [MROWS * CDIM];

// split-bf16 operands -- ALL stored in pre-swizzled tile-blocked layouts
__device__ __nv_bfloat16 g_xh [MROWS * CDIM];
__device__ __nv_bfloat16 g_xl [MROWS * CDIM];
__device__ __nv_bfloat16 g_ah [MROWS * CDIM];
__device__ __nv_bfloat16 g_al [MROWS * CDIM];
__device__ __nv_bfloat16 g_wqh[2 * CDIM * CDIM];
__device__ __nv_bfloat16 g_wql[2 * CDIM * CDIM];
__device__ __nv_bfloat16 g_wkh[2 * CDIM * CDIM];
__device__ __nv_bfloat16 g_wkl[2 * CDIM * CDIM];
__device__ __nv_bfloat16 g_wvh[CDIM * CDIM];
__device__ __nv_bfloat16 g_wvl[CDIM * CDIM];
__device__ __nv_bfloat16 g_woh[CDIM * CDIM];
__device__ __nv_bfloat16 g_wol[CDIM * CDIM];

// attention operands, split bf16, attention tile layout
__device__ __nv_bfloat16 g_qrh[MROWS * CDIM];
__device__ __nv_bfloat16 g_qrl[MROWS * CDIM];
__device__ __nv_bfloat16 g_qih[MROWS * CDIM];
__device__ __nv_bfloat16 g_qil[MROWS * CDIM];
__device__ __nv_bfloat16 g_krh[MROWS * CDIM];
__device__ __nv_bfloat16 g_krl[MROWS * CDIM];
__device__ __nv_bfloat16 g_kih[MROWS * CDIM];
__device__ __nv_bfloat16 g_kil[MROWS * CDIM];
__device__ __nv_bfloat16 g_vh [MROWS * CDIM];
__device__ __nv_bfloat16 g_vl [MROWS * CDIM];
__device__ float2 g_gate[HEADS * SEQ];

// ---------------- helpers ---------------------------------------------------
__device__ __forceinline__ uint32_t smem_u32(const void* p) {
    uint32_t a;
    asm("{ .reg .u64 t; cvta.to.shared.u64 t, %1; cvt.u32.u64 %0, t; }"
        : "=r"(a) : "l"(p));
    return a;
}
#define SWZ128(o) ((o) ^ (((o) >> 3) & 0x70))

// GEMM A-operand layout: [mb=row/128][kc=col/64][r=row%128][swizzled 128B row]
__device__ __forceinline__ size_t gemmA_off(int row, int col) {
    return ((size_t)((row >> 7) * 16 + (col >> 6)) << 14) +
           SWZ128((uint32_t)((row & 127) * 128 + (col & 63) * 2));
}
// Attention layout: [b][h][sb=t/64][r=t%64][swizzled 128B row]
__device__ __forceinline__ size_t att_off(int b, int h, int t, int d) {
    return ((size_t)((b * HEADS + h) * 32 + (t >> 6)) << 13) +
           SWZ128((uint32_t)((t & 63) * 128 + d * 2));
}

#define MBARRIER_INIT(mbar, count) \
    asm volatile("mbarrier.init.shared.b64 [%0], %1;" :: "r"((uint32_t)(mbar)), "r"((uint32_t)(count)) : "memory")
#define MBAR_EXPECT(mbar, bytes) \
    asm volatile("mbarrier.arrive.expect_tx.shared.b64 _, [%0], %1;" :: "r"((uint32_t)(mbar)), "r"((uint32_t)(bytes)) : "memory")

#define MBARRIER_WAIT_PARITY(mbar, parity) do { \
    uint32_t _m = (uint32_t)(mbar); uint32_t _p = (uint32_t)(parity); uint32_t _d; \
    asm volatile("{\n\t.reg .pred p;\n\t" \
        "mbarrier.try_wait.parity.acquire.cta.shared::cta.b64 p, [%1], %2;\n\t" \
        "selp.b32 %0, 1, 0, p;\n\t}" : "=r"(_d) : "r"(_m), "r"(_p) : "memory"); \
    if (!_d) { \
        asm volatile("{\n\t.reg .pred P1;\n\t" \
            "WL_%=:\n\t" \
            "mbarrier.try_wait.parity.acquire.cta.shared::cta.b64 P1, [%0], %1, 0x989680;\n\t" \
            "@P1 bra.uni WD_%=;\n\tbra.uni WL_%=;\n\tWD_%=:\n\t}" \
            :: "r"(_m), "r"(_p) : "memory"); \
    } } while (0)

__device__ __forceinline__ void bulk_g2s(uint32_t dst, const void* src,
                                         uint32_t bytes, uint32_t mbar) {
    asm volatile(
        "cp.async.bulk.shared::cluster.global.mbarrier::complete_tx::bytes [%0], [%1], %2, [%3];"
        :: "r"(dst), "l"(src), "r"(bytes), "r"(mbar) : "memory");
}

__device__ __forceinline__ void ldsm_x4(uint32_t& r0, uint32_t& r1,
                                        uint32_t& r2, uint32_t& r3, uint32_t addr) {
    asm volatile("ldmatrix.sync.aligned.m8n8.x4.shared.b16 {%0,%1,%2,%3}, [%4];"
                 : "=r"(r0), "=r"(r1), "=r"(r2), "=r"(r3) : "r"(addr));
}
__device__ __forceinline__ void ldsm_x4_t(uint32_t& r0, uint32_t& r1,
                                          uint32_t& r2, uint32_t& r3, uint32_t addr) {
    asm volatile("ldmatrix.sync.aligned.m8n8.x4.trans.shared.b16 {%0,%1,%2,%3}, [%4];"
                 : "=r"(r0), "=r"(r1), "=r"(r2), "=r"(r3) : "r"(addr));
}

__device__ __forceinline__ void mma_bf16(float* c, const uint32_t* a,
                                         uint32_t b0, uint32_t b1) {
    asm volatile(
        "mma.sync.aligned.m16n8k16.row.col.f32.bf16.bf16.f32 "
        "{%0,%1,%2,%3}, {%4,%5,%6,%7}, {%8,%9}, {%0,%1,%2,%3};"
        : "+f"(c[0]), "+f"(c[1]), "+f"(c[2]), "+f"(c[3])
        : "r"(a[0]), "r"(a[1]), "r"(a[2]), "r"(a[3]), "r"(b0), "r"(b1));
}

__device__ __forceinline__ uint32_t pack_bf16(float a, float b) {
    __nv_bfloat162 t = __float22bfloat162_rn(make_float2(a, b));
    return *reinterpret_cast<uint32_t*>(&t);
}

// ---------------- split-bf16 GEMM: C[M,N] = A[M,K] * B[N,K]^T ---------------
// Block tile 128x256, 8 warps of 64x64. K-chunk 64. cp.async.bulk + mbarrier.
#define BK       64
#define NCH      (KDIM / BK)             // 16
#define A_TB     16384
#define B_TB     32768
#define STG_B    (2 * A_TB + 2 * B_TB)   // 98304
#define GEMM_SMEM (1024 + 2 * STG_B)     // 197632

__global__ __launch_bounds__(256, 1)
void gemm_bf16x3(const __nv_bfloat16* __restrict__ Ah, const __nv_bfloat16* __restrict__ Al,
                 const __nv_bfloat16* __restrict__ Bh, const __nv_bfloat16* __restrict__ Bl,
                 float* __restrict__ Cm, int N) {
    extern __shared__ char smem[];
    const uint32_t sb = smem_u32(smem);
    const int tid = threadIdx.x, wid = tid >> 5, lane = tid & 31;
    const int m0 = blockIdx.y * 128, n0 = blockIdx.x * 256;
    const int wm = (wid & 1) * 64;
    const int wn = (wid >> 1) * 64;

    const char* cAh = (const char*)Ah;
    const char* cAl = (const char*)Al;
    const char* cBh = (const char*)Bh;
    const char* cBl = (const char*)Bl;
    const size_t mbB = ((size_t)blockIdx.y * 16) << 14;       // A row-block base
    const size_t nbB0 = ((size_t)(blockIdx.x * 2) * 16) << 14; // B row-block bases
    const size_t nbB1 = ((size_t)(blockIdx.x * 2 + 1) * 16) << 14;

    if (tid == 0) { MBARRIER_INIT(sb, 1); MBARRIER_INIT(sb + 8, 1); }
    __syncthreads();

    auto issue = [&](int chunk, int buf) {
        const uint32_t st = sb + 1024 + buf * STG_B;
        const uint32_t bar = sb + buf * 8;
        const size_t kB = ((size_t)chunk) << 14;
        MBAR_EXPECT(bar, STG_B);
        bulk_g2s(st,             cAh + mbB + kB,  A_TB, bar);
        bulk_g2s(st + A_TB,      cAl + mbB + kB,  A_TB, bar);
        bulk_g2s(st + 2 * A_TB,          cBh + nbB0 + kB, A_TB, bar);
        bulk_g2s(st + 2 * A_TB + A_TB,   cBh + nbB1 + kB, A_TB, bar);
        bulk_g2s(st + 2 * A_TB + B_TB,        cBl + nbB0 + kB, A_TB, bar);
        bulk_g2s(st + 2 * A_TB + B_TB + A_TB, cBl + nbB1 + kB, A_TB, bar);
    };

    if (tid == 0) { issue(0, 0); issue(1, 1); }

    float acc[4][8][4];
#pragma unroll
    for (int i = 0; i < 4; i++)
#pragma unroll
        for (int j = 0; j < 8; j++)
#pragma unroll
            for (int e = 0; e < 4; e++) acc[i][j][e] = 0.f;

    const int a_row = (lane & 15);
    const uint32_t a_cb = (uint32_t)((lane >> 4) * 16);
    const int b_row = ((lane >> 4) & 1) * 8 + (lane & 7);
    const uint32_t b_cb = (uint32_t)(((lane >> 3) & 1) * 16);

    for (int i = 0; i < NCH; i++) {
        MBARRIER_WAIT_PARITY(sb + (i & 1) * 8, (i >> 1) & 1);

        const uint32_t st = sb + 1024 + (i & 1) * STG_B;
        const uint32_t aH = st, aL = st + A_TB;
        const uint32_t bH = st + 2 * A_TB, bL = st + 2 * A_TB + B_TB;

#pragma unroll
        for (int ks = 0; ks < 4; ks++) {
            const uint32_t kb = (uint32_t)(ks * 32);
            uint32_t ah[4][4], al[4][4];
#pragma unroll
            for (int mi = 0; mi < 4; mi++) {
                uint32_t off = SWZ128((uint32_t)((wm + mi * 16 + a_row) * 128) + kb + a_cb);
                ldsm_x4(ah[mi][0], ah[mi][1], ah[mi][2], ah[mi][3], aH + off);
                ldsm_x4(al[mi][0], al[mi][1], al[mi][2], al[mi][3], aL + off);
            }
#pragma unroll
            for (int ng = 0; ng < 4; ng++) {
                uint32_t off = SWZ128((uint32_t)((wn + ng * 16 + b_row) * 128) + kb + b_cb);
                uint32_t bh[4], bl[4];
                ldsm_x4(bh[0], bh[1], bh[2], bh[3], bH + off);
                ldsm_x4(bl[0], bl[1], bl[2], bl[3], bL + off);
#pragma unroll
                for (int mi = 0; mi < 4; mi++) {
                    mma_bf16(acc[mi][2 * ng],     ah[mi], bh[0], bh[1]);
                    mma_bf16(acc[mi][2 * ng],     ah[mi], bl[0], bl[1]);
                    mma_bf16(acc[mi][2 * ng],     al[mi], bh[0], bh[1]);
                    mma_bf16(acc[mi][2 * ng + 1], ah[mi], bh[2], bh[3]);
                    mma_bf16(acc[mi][2 * ng + 1], ah[mi], bl[2], bl[3]);
                    mma_bf16(acc[mi][2 * ng + 1], al[mi], bh[2], bh[3]);
                }
            }
        }
        __syncthreads();
        if (i + 2 < NCH && tid == 0) issue(i + 2, i & 1);
    }

    const int cr = lane >> 2;
    const int cc = (lane & 3) * 2;
#pragma unroll
    for (int mi = 0; mi < 4; mi++) {
#pragma unroll
        for (int nj = 0; nj < 8; nj++) {
            const int r = m0 + wm + mi * 16 + cr;
            const int c = n0 + wn + nj * 8 + cc;
            *(float2*)&Cm[(size_t)r * N + c] = make_float2(acc[mi][nj][0], acc[mi][nj][1]);
            *(float2*)&Cm[(size_t)(r + 8) * N + c] = make_float2(acc[mi][nj][2], acc[mi][nj][3]);
        }
    }
}

// ---------------- fp32 -> (hi,lo) bf16 split, GEMM-A tiled layout ----------
__global__ __launch_bounds__(256)
void convert_split_gemm(const float* __restrict__ src, __nv_bfloat16* __restrict__ hi,
                        __nv_bfloat16* __restrict__ lo) {
    int i2 = blockIdx.x * 256 + threadIdx.x;       // one per 2 elems
    int row = i2 >> 9, col = (i2 & 511) * 2;
    float2 v = *(const float2*)&src[(size_t)row * CDIM + col];
    __nv_bfloat16 h0 = __float2bfloat16(v.x), h1 = __float2bfloat16(v.y);
    size_t off = gemmA_off(row, col);
    *(uint32_t*)((char*)hi + off) = pack_bf16(__bfloat162float(h0), __bfloat162float(h1));
    *(uint32_t*)((char*)lo + off) = pack_bf16(v.x - __bfloat162float(h0),
                                              v.y - __bfloat162float(h1));
}

// fp32 [4096x1024] -> hi/lo in ATTENTION tiled layout (for V)
__global__ __launch_bounds__(256)
void convert_split_att(const float* __restrict__ src, __nv_bfloat16* __restrict__ hi,
                       __nv_bfloat16* __restrict__ lo) {
    int i2 = blockIdx.x * 256 + threadIdx.x;
    int bt = i2 >> 9, col = (i2 & 511) * 2;
    int b = bt >> 11, t = bt & (SEQ - 1);
    int h = col >> 6, d = col & 63;
    float2 v = *(const float2*)&src[(size_t)bt * CDIM + col];
    __nv_bfloat16 h0 = __float2bfloat16(v.x), h1 = __float2bfloat16(v.y);
    size_t off = att_off(b, h, t, d);
    *(uint32_t*)((char*)hi + off) = pack_bf16(__bfloat162float(h0), __bfloat162float(h1));
    *(uint32_t*)((char*)lo + off) = pack_bf16(v.x - __bfloat162float(h0),
                                              v.y - __bfloat162float(h1));
}

// ---------------- weight transpose + split -> GEMM-A tiled layout ----------
__global__ __launch_bounds__(256)
void transpose_split(const float* __restrict__ W, __nv_bfloat16* __restrict__ Hh,
                     __nv_bfloat16* __restrict__ Hl, int K, int N) {
    __shared__ float t[32][33];
    const int tx = threadIdx.x, ty = threadIdx.y;
    const int n0 = blockIdx.x * 32, k0 = blockIdx.y * 32;
#pragma unroll
    for (int i = 0; i < 32; i += 8)
        t[ty + i][tx] = W[(size_t)(k0 + ty + i) * N + n0 + tx];
    __syncthreads();
#pragma unroll
    for (int i = 0; i < 32; i += 8) {
        float v = t[tx][ty + i];
        __nv_bfloat16 h = __float2bfloat16(v);
        size_t off = gemmA_off(n0 + ty + i, k0 + tx);
        *(__nv_bfloat16*)((char*)Hh + off) = h;
        *(__nv_bfloat16*)((char*)Hl + off) = __float2bfloat16(v - __bfloat162float(h));
    }
}

// ---------------- amp/phase transform -> split bf16, attention layout -------
__device__ __forceinline__ float softplus_f(float a) {
    return (a > 20.f) ? a : log1pf(expf(a));
}
__device__ __forceinline__ void split_store(float a, float b, __nv_bfloat16* H,
                                            __nv_bfloat16* L, size_t off) {
    __nv_bfloat16 ha = __float2bfloat16(a), hb = __float2bfloat16(b);
    *(uint32_t*)((char*)H + off) = pack_bf16(__bfloat162float(ha), __bfloat162float(hb));
    *(uint32_t*)((char*)L + off) = pack_bf16(a - __bfloat162float(ha),
                                             b - __bfloat162float(hb));
}

__global__ __launch_bounds__(256)
void transform_qk_bf16() {
    int i2 = blockIdx.x * 256 + threadIdx.x;
    int c2 = i2 * 2;
    int bt = c2 >> 10;
    int c  = c2 & 1023;
    int b = bt >> 11, t = bt & (SEQ - 1);
    int h = c >> 6, d = c & 63;
    size_t rbase = (size_t)bt * (2 * CDIM);
    size_t off = att_off(b, h, t, d);

    float qa0 = g_qraw[rbase + c],        qa1 = g_qraw[rbase + c + 1];
    float qp0 = g_qraw[rbase + CDIM + c], qp1 = g_qraw[rbase + CDIM + c + 1];
    float ka0 = g_kraw[rbase + c],        ka1 = g_kraw[rbase + c + 1];
    float kp0 = g_kraw[rbase + CDIM + c], kp1 = g_kraw[rbase + CDIM + c + 1];

    float qs0 = softplus_f(qa0), qs1 = softplus_f(qa1);
    float ks0 = softplus_f(ka0), ks1 = softplus_f(ka1);
    float s0, c0, s1, c1, s2, c2f, s3, c3;
    sincosf(qp0, &s0, &c0); sincosf(qp1, &s1, &c1);
    sincosf(kp0, &s2, &c2f); sincosf(kp1, &s3, &c3);

    split_store(qs0 * c0, qs1 * c1, g_qrh, g_qrl, off);
    split_store(qs0 * s0, qs1 * s1, g_qih, g_qil, off);
    split_store(ks0 * c2f, ks1 * c3, g_krh, g_krl, off);
    split_store(ks0 * s2, ks1 * s3, g_kih, g_kil, off);
}

__global__ void gate_init(const float* __restrict__ theta) {
    int i = blockIdx.x * 256 + threadIdx.x;
    int h = i >> 11, s = i & (SEQ - 1);
    float th = theta[h] * (1.0f / GAMMA_F);
    float sn, cs;
    sincosf(th * (float)s, &sn, &cs);
    g_gate[i] = make_float2(cs, sn);
}

// ---------------- tensor-core flash attention with moiré gate ---------------
#define AQT 128
#define AST 64
#define AQ_TILE 16384
#define AKV_TILE 8192
#define AKV_BUF (6 * AKV_TILE)              // 49152
#define ATT_SMEM (1024 + 4 * AQ_TILE + 2 * AKV_BUF)  // 164864

__global__ __launch_bounds__(256)
void attn_mma() {
    extern __shared__ char smem[];
    const uint32_t sb = smem_u32(smem);
    const uint32_t sQ  = sb + 1024;
    const uint32_t sKV = sQ + 4 * AQ_TILE;

    const int tid = threadIdx.x, w = tid >> 5, lane = tid & 31;
    const int q0 = (int)(gridDim.x - 1 - blockIdx.x) * AQT;
    const int h = blockIdx.y, b = blockIdx.z;
    const int nS = q0 / AST + 2;

    const size_t bhB = ((size_t)((b * HEADS + h) * 32)) << 13;  // (b,h) base bytes

    if (tid == 0) {
        MBARRIER_INIT(sb, 1);        // Q
        MBARRIER_INIT(sb + 8, 1);    // KV buf 0
        MBARRIER_INIT(sb + 16, 1);   // KV buf 1
    }
    __syncthreads();

    auto issue_kv = [&](int chunk, int buf) {
        const uint32_t st = sKV + buf * AKV_BUF;
        const uint32_t bar = sb + 8 + buf * 8;
        const size_t src = bhB + (((size_t)chunk) << 13);
        MBAR_EXPECT(bar, AKV_BUF);
        bulk_g2s(st,                (const char*)g_krh + src, AKV_TILE, bar);
        bulk_g2s(st + AKV_TILE,     (const char*)g_krl + src, AKV_TILE, bar);
        bulk_g2s(st + 2 * AKV_TILE, (const char*)g_kih + src, AKV_TILE, bar);
        bulk_g2s(st + 3 * AKV_TILE, (const char*)g_kil + src, AKV_TILE, bar);
        bulk_g2s(st + 4 * AKV_TILE, (const char*)g_vh  + src, AKV_TILE, bar);
        bulk_g2s(st + 5 * AKV_TILE, (const char*)g_vl  + src, AKV_TILE, bar);
    };

    if (tid == 0) {
        const size_t qsrc = bhB + (((size_t)(q0 >> 6)) << 13);
        MBAR_EXPECT(sb, 4 * AQ_TILE);
        bulk_g2s(sQ,               (const char*)g_qrh + qsrc, AQ_TILE, sb);
        bulk_g2s(sQ + AQ_TILE,     (const char*)g_qrl + qsrc, AQ_TILE, sb);
        bulk_g2s(sQ + 2 * AQ_TILE, (const char*)g_qih + qsrc, AQ_TILE, sb);
        bulk_g2s(sQ + 3 * AQ_TILE, (const char*)g_qil + qsrc, AQ_TILE, sb);
        issue_kv(0, 0);
        issue_kv(1, 1);
    }

    const int a_row = lane & 15;
    const uint32_t a_cb = (uint32_t)((lane >> 4) * 16);
    const int b_row = ((lane >> 4) & 1) * 8 + (lane & 7);
    const uint32_t b_cb = (uint32_t)(((lane >> 3) & 1) * 16);

    const int t0g = q0 + w * 16 + (lane >> 2);
    const int t1g = t0g + 8;
    const float2 gt0 = g_gate[h * SEQ + t0g];
    const float2 gt1 = g_gate[h * SEQ + t1g];

    float m0 = -INFINITY, m1 = -INFINITY, l0 = 0.f, l1 = 0.f;
    float oacc[8][4];
#pragma unroll
    for (int f = 0; f < 8; f++)
#pragma unroll
        for (int e = 0; e < 4; e++) oacc[f][e] = 0.f;

    MBARRIER_WAIT_PARITY(sb, 0);   // Q ready

    for (int i = 0; i < nS; i++) {
        MBARRIER_WAIT_PARITY(sb + 8 + (i & 1) * 8, (i >> 1) & 1);

        const int s0 = i * AST;
        const uint32_t kb0 = sKV + (i & 1) * AKV_BUF;
        const uint32_t kRH = kb0, kRL = kb0 + AKV_TILE;
        const uint32_t kIH = kb0 + 2 * AKV_TILE, kIL = kb0 + 3 * AKV_TILE;
        const uint32_t vH = kb0 + 4 * AKV_TILE, vL = kb0 + 5 * AKV_TILE;

        float sacc[8][4];
#pragma unroll
        for (int f = 0; f < 8; f++)
#pragma unroll
            for (int e = 0; e < 4; e++) sacc[f][e] = 0.f;

#pragma unroll
        for (int jd = 0; jd < 4; jd++) {
            const uint32_t kb = (uint32_t)(jd * 32);
            const uint32_t offA = SWZ128((uint32_t)((w * 16 + a_row) * 128) + kb + a_cb);
            uint32_t arh[4], arl[4], aih[4], ail[4];
            ldsm_x4(arh[0], arh[1], arh[2], arh[3], sQ + offA);
            ldsm_x4(arl[0], arl[1], arl[2], arl[3], sQ + AQ_TILE + offA);
            ldsm_x4(aih[0], aih[1], aih[2], aih[3], sQ + 2 * AQ_TILE + offA);
            ldsm_x4(ail[0], ail[1], ail[2], ail[3], sQ + 3 * AQ_TILE + offA);
#pragma unroll
            for (int g = 0; g < 4; g++) {
                const uint32_t offB = SWZ128((uint32_t)((g * 16 + b_row) * 128) + kb + b_cb);
                uint32_t rh[4], rl[4], ih[4], il[4];
                ldsm_x4(rh[0], rh[1], rh[2], rh[3], kRH + offB);
                ldsm_x4(rl[0], rl[1], rl[2], rl[3], kRL + offB);
                ldsm_x4(ih[0], ih[1], ih[2], ih[3], kIH + offB);
                ldsm_x4(il[0], il[1], il[2], il[3], kIL + offB);
                mma_bf16(sacc[2 * g],     arh, rh[0], rh[1]);
                mma_bf16(sacc[2 * g],     arl, rh[0], rh[1]);
                mma_bf16(sacc[2 * g],     arh, rl[0], rl[1]);
                mma_bf16(sacc[2 * g],     aih, ih[0], ih[1]);
                mma_bf16(sacc[2 * g],     ail, ih[0], ih[1]);
                mma_bf16(sacc[2 * g],     aih, il[0], il[1]);
                mma_bf16(sacc[2 * g + 1], arh, rh[2], rh[3]);
                mma_bf16(sacc[2 * g + 1], arl, rh[2], rh[3]);
                mma_bf16(sacc[2 * g + 1], arh, rl[2], rl[3]);
                mma_bf16(sacc[2 * g + 1], aih, ih[2], ih[3]);
                mma_bf16(sacc[2 * g + 1], ail, ih[2], ih[3]);
                mma_bf16(sacc[2 * g + 1], aih, il[2], il[3]);
            }
        }

        float pm0 = -INFINITY, pm1 = -INFINITY;
#pragma unroll
        for (int f = 0; f < 8; f++) {
            const int sb2 = s0 + f * 8 + (lane & 3) * 2;
            const float2 gs0 = g_gate[h * SEQ + sb2];
            const float2 gs1 = g_gate[h * SEQ + sb2 + 1];
            float v00 = sacc[f][0] * SCALE_F * (gs0.x * gt0.x + gs0.y * gt0.y);
            float v01 = sacc[f][1] * SCALE_F * (gs1.x * gt0.x + gs1.y * gt0.y);
            float v10 = sacc[f][2] * SCALE_F * (gs0.x * gt1.x + gs0.y * gt1.y);
            float v11 = sacc[f][3] * SCALE_F * (gs1.x * gt1.x + gs1.y * gt1.y);
            if (sb2 > t0g)     v00 = -INFINITY;
            if (sb2 + 1 > t0g) v01 = -INFINITY;
            if (sb2 > t1g)     v10 = -INFINITY;
            if (sb2 + 1 > t1g) v11 = -INFINITY;
            sacc[f][0] = v00; sacc[f][1] = v01; sacc[f][2] = v10; sacc[f][3] = v11;
            pm0 = fmaxf(pm0, fmaxf(v00, v01));
            pm1 = fmaxf(pm1, fmaxf(v10, v11));
        }
        pm0 = fmaxf(pm0, __shfl_xor_sync(0xffffffffu, pm0, 1));
        pm0 = fmaxf(pm0, __shfl_xor_sync(0xffffffffu, pm0, 2));
        pm1 = fmaxf(pm1, __shfl_xor_sync(0xffffffffu, pm1, 1));
        pm1 = fmaxf(pm1, __shfl_xor_sync(0xffffffffu, pm1, 2));

        const float mn0 = fmaxf(m0, pm0), mn1 = fmaxf(m1, pm1);
        const float cr0 = __expf(m0 - mn0), cr1 = __expf(m1 - mn1);
        float rs0 = 0.f, rs1 = 0.f;
#pragma unroll
        for (int f = 0; f < 8; f++) {
            sacc[f][0] = __expf(sacc[f][0] - mn0);
            sacc[f][1] = __expf(sacc[f][1] - mn0);
            sacc[f][2] = __expf(sacc[f][2] - mn1);
            sacc[f][3] = __expf(sacc[f][3] - mn1);
            rs0 += sacc[f][0] + sacc[f][1];
            rs1 += sacc[f][2] + sacc[f][3];
        }
        rs0 += __shfl_xor_sync(0xffffffffu, rs0, 1);
        rs0 += __shfl_xor_sync(0xffffffffu, rs0, 2);
        rs1 += __shfl_xor_sync(0xffffffffu, rs1, 1);
        rs1 += __shfl_xor_sync(0xffffffffu, rs1, 2);
        l0 = l0 * cr0 + rs0; m0 = mn0;
        l1 = l1 * cr1 + rs1; m1 = mn1;
#pragma unroll
        for (int f = 0; f < 8; f++) {
            oacc[f][0] *= cr0; oacc[f][1] *= cr0;
            oacc[f][2] *= cr1; oacc[f][3] *= cr1;
        }

#pragma unroll
        for (int j = 0; j < 4; j++) {
            float p00 = sacc[2 * j][0],     p01 = sacc[2 * j][1];
            float p02 = sacc[2 * j][2],     p03 = sacc[2 * j][3];
            float p10 = sacc[2 * j + 1][0], p11 = sacc[2 * j + 1][1];
            float p12 = sacc[2 * j + 1][2], p13 = sacc[2 * j + 1][3];
            float h00 = __bfloat162float(__float2bfloat16(p00));
            float h01 = __bfloat162float(__float2bfloat16(p01));
            float h02 = __bfloat162float(__float2bfloat16(p02));
            float h03 = __bfloat162float(__float2bfloat16(p03));
            float h10 = __bfloat162float(__float2bfloat16(p10));
            float h11 = __bfloat162float(__float2bfloat16(p11));
            float h12 = __bfloat162float(__float2bfloat16(p12));
            float h13 = __bfloat162float(__float2bfloat16(p13));
            uint32_t ph[4] = {pack_bf16(h00, h01), pack_bf16(h02, h03),
                              pack_bf16(h10, h11), pack_bf16(h12, h13)};
            uint32_t pl[4] = {pack_bf16(p00 - h00, p01 - h01), pack_bf16(p02 - h02, p03 - h03),
                              pack_bf16(p10 - h10, p11 - h11), pack_bf16(p12 - h12, p13 - h13)};
#pragma unroll
            for (int dg = 0; dg < 4; dg++) {
                const uint32_t offV = SWZ128((uint32_t)((16 * j + a_row) * 128) +
                                             (uint32_t)(dg * 32) + a_cb);
                uint32_t vh[4], vl[4];
                ldsm_x4_t(vh[0], vh[1], vh[2], vh[3], vH + offV);
                ldsm_x4_t(vl[0], vl[1], vl[2], vl[3], vL + offV);
                mma_bf16(oacc[2 * dg],     ph, vh[0], vh[1]);
                mma_bf16(oacc[2 * dg],     pl, vh[0], vh[1]);
                mma_bf16(oacc[2 * dg],     ph, vl[0], vl[1]);
                mma_bf16(oacc[2 * dg + 1], ph, vh[2], vh[3]);
                mma_bf16(oacc[2 * dg + 1], pl, vh[2], vh[3]);
                mma_bf16(oacc[2 * dg + 1], ph, vl[2], vl[3]);
            }
        }
        __syncthreads();
        if (i + 2 < nS && tid == 0) issue_kv(i + 2, i & 1);
    }

    // epilogue: normalize, write bf16 hi/lo in GEMM-A tiled layout (kc == h)
    const float iv0 = 1.0f / l0, iv1 = 1.0f / l1;
#pragma unroll
    for (int f = 0; f < 8; f++) {
        const int d = f * 8 + (lane & 3) * 2;
        float o00 = oacc[f][0] * iv0, o01 = oacc[f][1] * iv0;
        float o10 = oacc[f][2] * iv1, o11 = oacc[f][3] * iv1;
        float h00 = __bfloat162float(__float2bfloat16(o00));
        float h01 = __bfloat162float(__float2bfloat16(o01));
        float h10 = __bfloat162float(__float2bfloat16(o10));
        float h11 = __bfloat162float(__float2bfloat16(o11));
        size_t off0 = gemmA_off(b * SEQ + t0g, h * 64 + d);
        size_t off1 = gemmA_off(b * SEQ + t1g, h * 64 + d);
        *(uint32_t*)((char*)g_ah + off0) = pack_bf16(h00, h01);
        *(uint32_t*)((char*)g_al + off0) = pack_bf16(o00 - h00, o01 - h01);
        *(uint32_t*)((char*)g_ah + off1) = pack_bf16(h10, h11);
        *(uint32_t*)((char*)g_al + off1) = pack_bf16(o10 - h10, o11 - h11);
    }
}

// ---------------- launch ---------------------------------------------------
extern "C" void kernel_launch(void* const* d_in, const int* in_sizes, int n_in,
                              void* d_out, int out_size) {
    const float* x     = (const float*)d_in[0];
    const float* Wq    = (const float*)d_in[1];
    const float* Wk    = (const float*)d_in[2];
    const float* Wv    = (const float*)d_in[3];
    const float* Wo    = (const float*)d_in[4];
    const float* theta = (const float*)d_in[5];
    float* out = (float*)d_out;

    float *qraw, *kraw, *v;
    __nv_bfloat16 *xh, *xl, *ah, *al, *vh, *vl;
    __nv_bfloat16 *wqh, *wql, *wkh, *wkl, *wvh, *wvl, *woh, *wol;
    cudaGetSymbolAddress((void**)&qraw, g_qraw);
    cudaGetSymbolAddress((void**)&kraw, g_kraw);
    cudaGetSymbolAddress((void**)&v,    g_v);
    cudaGetSymbolAddress((void**)&xh,  g_xh);
    cudaGetSymbolAddress((void**)&xl,  g_xl);
    cudaGetSymbolAddress((void**)&ah,  g_ah);
    cudaGetSymbolAddress((void**)&al,  g_al);
    cudaGetSymbolAddress((void**)&vh,  g_vh);
    cudaGetSymbolAddress((void**)&vl,  g_vl);
    cudaGetSymbolAddress((void**)&wqh, g_wqh);
    cudaGetSymbolAddress((void**)&wql, g_wql);
    cudaGetSymbolAddress((void**)&wkh, g_wkh);
    cudaGetSymbolAddress((void**)&wkl, g_wkl);
    cudaGetSymbolAddress((void**)&wvh, g_wvh);
    cudaGetSymbolAddress((void**)&wvl, g_wvl);
    cudaGetSymbolAddress((void**)&woh, g_woh);
    cudaGetSymbolAddress((void**)&wol, g_wol);

    cudaFuncSetAttribute(gemm_bf16x3,
                         cudaFuncAttributeMaxDynamicSharedMemorySize, GEMM_SMEM);
    cudaFuncSetAttribute(attn_mma,
                         cudaFuncAttributeMaxDynamicSharedMemorySize, ATT_SMEM);

    dim3 tblk(32, 8);

    convert_split_gemm<<<MROWS * CDIM / 2 / 256, 256>>>(x, xh, xl);
    transpose_split<<<dim3(2 * CDIM / 32, CDIM / 32), tblk>>>(Wq, wqh, wql, CDIM, 2 * CDIM);
    gemm_bf16x3<<<dim3(2 * CDIM / 256, MROWS / 128), 256, GEMM_SMEM>>>(xh, xl, wqh, wql, qraw, 2 * CDIM);
    transpose_split<<<dim3(2 * CDIM / 32, CDIM / 32), tblk>>>(Wk, wkh, wkl, CDIM, 2 * CDIM);
    gemm_bf16x3<<<dim3(2 * CDIM / 256, MROWS / 128), 256, GEMM_SMEM>>>(xh, xl, wkh, wkl, kraw, 2 * CDIM);
    transpose_split<<<dim3(CDIM / 32, CDIM / 32), tblk>>>(Wv, wvh, wvl, CDIM, CDIM);
    gemm_bf16x3<<<dim3(CDIM / 256, MROWS / 128), 256, GEMM_SMEM>>>(xh, xl, wvh, wvl, v, CDIM);

    transform_qk_bf16<<<MROWS * CDIM / 2 / 256, 256>>>();
    convert_split_att<<<MROWS * CDIM / 2 / 256, 256>>>(v, vh, vl);
    gate_init<<<HEADS * SEQ / 256, 256>>>(theta);

    attn_mma<<<dim3(SEQ / AQT, HEADS, BATCH), 256, ATT_SMEM>>>();

    transpose_split<<<dim3(CDIM / 32, CDIM / 32), tblk>>>(Wo, woh, wol, CDIM, CDIM);
    gemm_bf16x3<<<dim3(CDIM / 256, MROWS / 128), 256, GEMM_SMEM>>>(ah, al, woh, wol, out, CDIM);
}